// round 2
// baseline (speedup 1.0000x reference)
#include <cuda_runtime.h>
#include <cstdint>
#include <cstddef>

#define S_LEN   2048
#define D_KDIM  64
#define BH      32
#define MQ      16
#define NK      128
#define NTILES  (S_LEN / NK)      // 16
#define THREADS 256
#define KS_STRIDE 68              // floats per K/V smem row (pad for banks)
#define P_STRIDE  2056            // floats per p smem row (2048 + 8 pad)

// smem layout (in floats)
#define OFF_Q   0
#define OFF_K   (OFF_Q + MQ * D_KDIM)          // 1024
#define OFF_V   (OFF_K + NK * KS_STRIDE)       // 9728
#define OFF_P   (OFF_V + NK * KS_STRIDE)       // 18432
#define OFF_SUM (OFF_P + MQ * P_STRIDE)        // 51328
#define SMEM_FLOATS (OFF_SUM + MQ)             // 51344
#define SMEM_BYTES  (SMEM_FLOATS * 4)          // 205376 bytes (< 227KB limit)

typedef unsigned long long ull;

// mask storage kind: 1 = byte-wide (uint8/bool), 0 = word-wide (int32 or float32)
__device__ int g_mask_wide;

// pack two fp32 into a 64-bit f32x2 operand
__device__ __forceinline__ ull pk(float lo, float hi) {
    ull r;
    asm("mov.b64 %0, {%1, %2};" : "=l"(r) : "f"(lo), "f"(hi));
    return r;
}
// d = a * b + d  (packed 2-wide fp32 FMA — doubles fp32 rate on sm_103a)
__device__ __forceinline__ void fma2(ull& d, ull a, ull b) {
    asm("fma.rn.f32x2 %0, %1, %2, %0;" : "+l"(d) : "l"(a), "l"(b));
}
__device__ __forceinline__ float plo(ull v) {
    float f;
    asm("{ .reg .b32 hi; mov.b64 {%0, hi}, %1; }" : "=f"(f) : "l"(v));
    return f;
}
__device__ __forceinline__ float phi(ull v) {
    float f;
    asm("{ .reg .b32 lo; mov.b64 {lo, %0}, %1; }" : "=f"(f) : "l"(v));
    return f;
}

// Classify mask element width from the first 1024 32-bit words.
//  - int32 bool: every word is 0 or 1            -> wide
//  - fp32 bool:  every word is 0 or 0x3F800000   -> wide
//  - uint8 bool: words are 4 packed random 0/1 bytes -> neither pattern -> byte
__global__ void detect_mask_kind_kernel(const unsigned* __restrict__ mw) {
    __shared__ int s_i32bad, s_f32bad;
    if (threadIdx.x == 0) { s_i32bad = 0; s_f32bad = 0; }
    __syncthreads();
    for (int i = threadIdx.x; i < 1024; i += blockDim.x) {
        unsigned w = mw[i];
        if (w > 1u)                      atomicOr(&s_i32bad, 1);
        if (w != 0u && w != 0x3F800000u) atomicOr(&s_f32bad, 1);
    }
    __syncthreads();
    if (threadIdx.x == 0)
        g_mask_wide = (!s_i32bad || !s_f32bad) ? 1 : 0;   // 1 = 4-byte elems
}

__global__ void __launch_bounds__(THREADS, 1)
sdpa_fused_kernel(const float* __restrict__ Qg,
                  const float* __restrict__ Kg,
                  const float* __restrict__ Vg,
                  const unsigned char* __restrict__ Mg,
                  float* __restrict__ ctx_out,
                  float* __restrict__ w_out)
{
    extern __shared__ float sm[];
    float* Qs   = sm + OFF_Q;
    float* Ks   = sm + OFF_K;
    float* Vs   = sm + OFF_V;
    float* Ps   = sm + OFF_P;
    float* Sums = sm + OFF_SUM;

    const int t  = threadIdx.x;
    const int bh = blockIdx.y;
    const int q0 = blockIdx.x * MQ;
    const int qi = t >> 4;      // 0..15  query row within tile
    const int kg = t & 15;      // 0..15  k-group (S phase) / d-group (PV phase)

    const size_t row0 = (size_t)bh * S_LEN + q0;

    const int wide = g_mask_wide;    // uniform across grid

    // ---- load Q tile (16x64 fp32 = 256 float4) ----
    {
        const float4* qg4 = (const float4*)(Qg + row0 * D_KDIM);
        ((float4*)Qs)[t] = qg4[t];
    }

    const unsigned char* m8  = Mg + (row0 + qi) * (size_t)S_LEN;
    const unsigned*      m32 = (const unsigned*)Mg + (row0 + qi) * (size_t)S_LEN;

    ull c01 = 0, c23 = 0;   // context accumulators for (qi, d = kg*4 .. kg*4+3)
    float lsum = 0.f;       // partial row sum over this thread's k columns

    for (int kb = 0; kb < NTILES; ++kb) {
        // ---- load K,V tiles [128 x 64] into padded smem ----
        {
            const float4* kgm = (const float4*)(Kg + ((size_t)bh * S_LEN + kb * NK) * D_KDIM);
            const float4* vgm = (const float4*)(Vg + ((size_t)bh * S_LEN + kb * NK) * D_KDIM);
            float4* ks4 = (float4*)Ks;
            float4* vs4 = (float4*)Vs;
#pragma unroll
            for (int it = 0; it < 8; ++it) {
                int i   = t + it * THREADS;
                int row = i >> 4;
                int c4  = i & 15;
                ks4[row * 17 + c4] = kgm[i];
                vs4[row * 17 + c4] = vgm[i];
            }
        }
        __syncthreads();

        // ---- S phase: scores for (qi, k = kg + 16*j), j=0..7 ----
        // f32x2 pairs accumulate (even-d, odd-d) partial dots.
        ull acc[8];
#pragma unroll
        for (int j = 0; j < 8; ++j) acc[j] = 0;
        {
            const float4* qrow = (const float4*)(Qs + qi * D_KDIM);
#pragma unroll
            for (int dd4 = 0; dd4 < 16; ++dd4) {
                float4 q4 = qrow[dd4];
                ull q01 = pk(q4.x, q4.y);
                ull q23 = pk(q4.z, q4.w);
#pragma unroll
                for (int j = 0; j < 8; ++j) {
                    float4 k4 = ((const float4*)Ks)[(kg + 16 * j) * 17 + dd4];
                    fma2(acc[j], q01, pk(k4.x, k4.y));
                    fma2(acc[j], q23, pk(k4.z, k4.w));
                }
            }
        }
        // mask + exp + store unnormalized p to smem
#pragma unroll
        for (int j = 0; j < 8; ++j) {
            int k = kg + 16 * j;
            int masked = wide ? (m32[kb * NK + k] != 0u)
                              : (m8 [kb * NK + k] != 0);
            float s = (plo(acc[j]) + phi(acc[j])) * 0.125f;   // 1/sqrt(64)
            float p = masked ? 0.f : __expf(s);
            lsum += p;
            Ps[qi * P_STRIDE + kb * NK + k] = p;
        }
        __syncthreads();   // p visible; Ks reads done

        // ---- PV phase: context[qi][kg*4 .. +3] += p * V ----
        {
            const float*  prow = Ps + qi * P_STRIDE + kb * NK;
            const float4* vs4  = (const float4*)Vs;
#pragma unroll 8
            for (int k = 0; k < NK; ++k) {
                float w = prow[k];
                ull ww = pk(w, w);
                float4 v4 = vs4[k * 17 + kg];
                fma2(c01, ww, pk(v4.x, v4.y));
                fma2(c23, ww, pk(v4.z, v4.w));
            }
        }
        __syncthreads();   // Vs consumed before next tile overwrites
    }

    // ---- reduce row sums across the 16 kg lanes ----
#pragma unroll
    for (int o = 8; o; o >>= 1) lsum += __shfl_xor_sync(0xffffffffu, lsum, o);
    if (kg == 0) Sums[qi] = lsum;
    __syncthreads();

    // ---- write context (normalized) ----
    {
        float inv = 1.0f / Sums[qi];
        float4 c;
        c.x = plo(c01) * inv;
        c.y = phi(c01) * inv;
        c.z = plo(c23) * inv;
        c.w = phi(c23) * inv;
        ((float4*)(ctx_out + (row0 + qi) * D_KDIM))[kg] = c;
    }

    // ---- write weights (normalized), 16x2048 fp32 per CTA ----
    {
#pragma unroll
        for (int it = 0; it < 32; ++it) {
            int i   = t + it * THREADS;   // float4 index, 0..8191
            int wqi = i >> 9;             // /512 float4 per row
            int k4  = i & 511;
            float inv = 1.0f / Sums[wqi];
            float4 p4 = ((const float4*)(Ps + wqi * P_STRIDE))[k4];
            p4.x *= inv; p4.y *= inv; p4.z *= inv; p4.w *= inv;
            ((float4*)(w_out + (row0 + wqi) * (size_t)S_LEN))[k4] = p4;
        }
    }
}

extern "C" void kernel_launch(void* const* d_in, const int* in_sizes, int n_in,
                              void* d_out, int out_size)
{
    const float*         Q = (const float*)d_in[0];
    const float*         K = (const float*)d_in[1];
    const float*         V = (const float*)d_in[2];
    const unsigned char* M = (const unsigned char*)d_in[3];

    float* ctx = (float*)d_out;
    float* wts = (float*)d_out + (size_t)BH * S_LEN * D_KDIM;  // context first, then weights

    cudaFuncSetAttribute(sdpa_fused_kernel,
                         cudaFuncAttributeMaxDynamicSharedMemorySize, SMEM_BYTES);

    // classify mask element width (uint8 vs int32/fp32) on-device, then run
    detect_mask_kind_kernel<<<1, 256>>>((const unsigned*)M);

    dim3 grid(S_LEN / MQ, BH);   // (128, 32) = 4096 CTAs
    sdpa_fused_kernel<<<grid, THREADS, SMEM_BYTES>>>(Q, K, V, M, ctx, wts);
}

// round 3
// speedup vs baseline: 2.1658x; 2.1658x over previous
#include <cuda_runtime.h>
#include <cstdint>
#include <cstddef>

#define S_LEN   2048
#define D_KDIM  64
#define BH      32
#define MQ      16
#define THREADS 512
#define KC      1024          // k-chunk for S phase
#define DC      16            // d-chunk for S phase
#define KT_STRIDE 1028        // Kt row stride (floats)
#define P_STRIDE  2068        // Ps row stride (floats), %32==20 -> 2-way worst

// smem offsets (floats)
#define OFF_QT   0                                  // Qt[64][16]
#define OFF_KV   1024                               // 16*1028=16448 (Kt) / 16384 (V / partials)
#define OFF_P    (OFF_KV + 16448)                   // 17472 ; Ps[16][2068]
#define OFF_SRED (OFF_P + MQ * P_STRIDE)            // 50560 ; [16][16]
#define OFF_SUM  (OFF_SRED + 256)                   // 50816 ; [16]
#define SMEM_FLOATS (OFF_SUM + 16)                  // 50832
#define SMEM_BYTES  (SMEM_FLOATS * 4)               // 203328

typedef unsigned long long ull;

__device__ int g_mask_wide;

__device__ __forceinline__ ull pk(float lo, float hi) {
    ull r; asm("mov.b64 %0, {%1, %2};" : "=l"(r) : "f"(lo), "f"(hi)); return r;
}
__device__ __forceinline__ void fma2(ull& d, ull a, ull b) {
    asm("fma.rn.f32x2 %0, %1, %2, %0;" : "+l"(d) : "l"(a), "l"(b));
}
__device__ __forceinline__ float plo(ull v) {
    float f; asm("{ .reg .b32 hi; mov.b64 {%0, hi}, %1; }" : "=f"(f) : "l"(v)); return f;
}
__device__ __forceinline__ float phi(ull v) {
    float f; asm("{ .reg .b32 lo; mov.b64 {lo, %0}, %1; }" : "=f"(f) : "l"(v)); return f;
}

// Classify mask element width from the first 1024 32-bit words.
__global__ void detect_mask_kind_kernel(const unsigned* __restrict__ mw) {
    __shared__ int s_i32bad, s_f32bad;
    if (threadIdx.x == 0) { s_i32bad = 0; s_f32bad = 0; }
    __syncthreads();
    for (int i = threadIdx.x; i < 1024; i += blockDim.x) {
        unsigned w = mw[i];
        if (w > 1u)                      atomicOr(&s_i32bad, 1);
        if (w != 0u && w != 0x3F800000u) atomicOr(&s_f32bad, 1);
    }
    __syncthreads();
    if (threadIdx.x == 0) g_mask_wide = (!s_i32bad || !s_f32bad) ? 1 : 0;
}

__global__ void __launch_bounds__(THREADS, 1)
sdpa_fused_kernel(const float* __restrict__ Qg,
                  const float* __restrict__ Kg,
                  const float* __restrict__ Vg,
                  const unsigned char* __restrict__ Mg,
                  float* __restrict__ ctx_out,
                  float* __restrict__ w_out)
{
    extern __shared__ float sm[];
    float* Qt   = sm + OFF_QT;
    float* KV   = sm + OFF_KV;
    float* Ps   = sm + OFF_P;
    float* Sred = sm + OFF_SRED;
    float* Sums = sm + OFF_SUM;

    const int t  = threadIdx.x;
    const int w  = t >> 5;       // warp 0..15
    const int l  = t & 31;
    const int qg = l >> 3;       // 0..3  : q-group (4 q rows each)
    const int kg = l & 7;        // 0..7  : k-group (S) / d-group (PV)

    const int bh = blockIdx.y;
    const int q0 = blockIdx.x * MQ;
    const size_t row0 = (size_t)bh * S_LEN + q0;
    const int wide = g_mask_wide;

    // ---- stage Q transposed: Qt[d][q] ----
    if (t < 256) {
        int q = t >> 4, d4 = (t & 15) * 4;
        float4 v = *(const float4*)(Qg + (row0 + q) * D_KDIM + d4);
        Qt[(d4 + 0) * MQ + q] = v.x;
        Qt[(d4 + 1) * MQ + q] = v.y;
        Qt[(d4 + 2) * MQ + q] = v.z;
        Qt[(d4 + 3) * MQ + q] = v.w;
    }

    float lsum[4] = {0.f, 0.f, 0.f, 0.f};
    ull ctx[4][4] = {};   // [q][dpair]: d = {dg*4+0,1},{dg*4+2,3},{32+dg*4+0,1},{32+dg*4+2,3}

    for (int kc = 0; kc < S_LEN / KC; ++kc) {
        const int kbase = kc * KC;

        // ================= S phase =================
        ull acc[4][4] = {};   // [q][kpair]: k = {kg*4+0,1},{+2,3},{32+kg*4+0,1},{+2,3}
        for (int dc = 0; dc < D_KDIM / DC; ++dc) {
            __syncthreads();   // previous KV users done (also orders Qt staging on first pass)
            // stage Kt[16][KC] transposed for d = dc*16..+15
            {
                const float* ksrc = Kg + ((size_t)bh * S_LEN + kbase) * D_KDIM + dc * DC;
#pragma unroll
                for (int rr = 0; rr < 2; ++rr) {
                    int r = t + rr * THREADS;            // k row 0..1023
                    const float4* src = (const float4*)(ksrc + (size_t)r * D_KDIM);
#pragma unroll
                    for (int j4 = 0; j4 < 4; ++j4) {
                        float4 v = src[j4];
                        KV[(j4 * 4 + 0) * KT_STRIDE + r] = v.x;
                        KV[(j4 * 4 + 1) * KT_STRIDE + r] = v.y;
                        KV[(j4 * 4 + 2) * KT_STRIDE + r] = v.z;
                        KV[(j4 * 4 + 3) * KT_STRIDE + r] = v.w;
                    }
                }
            }
            __syncthreads();
            // compute: warp w covers k in [w*64, w*64+64)
            const int kw = w * 64 + kg * 4;
#pragma unroll
            for (int dl = 0; dl < DC; ++dl) {
                int d = dc * DC + dl;
                float4 qv = *(const float4*)(Qt + d * MQ + qg * 4);
                float4 ka = *(const float4*)(KV + dl * KT_STRIDE + kw);
                float4 kb = *(const float4*)(KV + dl * KT_STRIDE + kw + 32);
                ull k01 = pk(ka.x, ka.y), k23 = pk(ka.z, ka.w);
                ull k45 = pk(kb.x, kb.y), k67 = pk(kb.z, kb.w);
                ull qq;
                qq = pk(qv.x, qv.x);
                fma2(acc[0][0], qq, k01); fma2(acc[0][1], qq, k23);
                fma2(acc[0][2], qq, k45); fma2(acc[0][3], qq, k67);
                qq = pk(qv.y, qv.y);
                fma2(acc[1][0], qq, k01); fma2(acc[1][1], qq, k23);
                fma2(acc[1][2], qq, k45); fma2(acc[1][3], qq, k67);
                qq = pk(qv.z, qv.z);
                fma2(acc[2][0], qq, k01); fma2(acc[2][1], qq, k23);
                fma2(acc[2][2], qq, k45); fma2(acc[2][3], qq, k67);
                qq = pk(qv.w, qv.w);
                fma2(acc[3][0], qq, k01); fma2(acc[3][1], qq, k23);
                fma2(acc[3][2], qq, k45); fma2(acc[3][3], qq, k67);
            }
        }

        // ================= mask + exp + store p =================
        {
            const int kA = kbase + w * 64 + kg * 4;   // first 4-k block
#pragma unroll
            for (int q = 0; q < 4; ++q) {
                int qrow = qg * 4 + q;
                size_t mbase = (row0 + qrow) * (size_t)S_LEN + kA;
                const unsigned char* m8  = Mg + mbase;
                const unsigned*      m32 = (const unsigned*)Mg + mbase;
                float* pdst = Ps + qrow * P_STRIDE + kA;
                float s0 = plo(acc[q][0]) * 0.125f, s1 = phi(acc[q][0]) * 0.125f;
                float s2 = plo(acc[q][1]) * 0.125f, s3 = phi(acc[q][1]) * 0.125f;
                float s4 = plo(acc[q][2]) * 0.125f, s5 = phi(acc[q][2]) * 0.125f;
                float s6 = plo(acc[q][3]) * 0.125f, s7 = phi(acc[q][3]) * 0.125f;
                int b0, b1, b2, b3, b4, b5, b6, b7;
                if (wide) {
                    b0 = m32[0] != 0u; b1 = m32[1] != 0u; b2 = m32[2] != 0u; b3 = m32[3] != 0u;
                    b4 = m32[32] != 0u; b5 = m32[33] != 0u; b6 = m32[34] != 0u; b7 = m32[35] != 0u;
                } else {
                    b0 = m8[0] != 0; b1 = m8[1] != 0; b2 = m8[2] != 0; b3 = m8[3] != 0;
                    b4 = m8[32] != 0; b5 = m8[33] != 0; b6 = m8[34] != 0; b7 = m8[35] != 0;
                }
                float4 pA, pB;
                pA.x = b0 ? 0.f : __expf(s0);  pA.y = b1 ? 0.f : __expf(s1);
                pA.z = b2 ? 0.f : __expf(s2);  pA.w = b3 ? 0.f : __expf(s3);
                pB.x = b4 ? 0.f : __expf(s4);  pB.y = b5 ? 0.f : __expf(s5);
                pB.z = b6 ? 0.f : __expf(s6);  pB.w = b7 ? 0.f : __expf(s7);
                lsum[q] += (pA.x + pA.y) + (pA.z + pA.w) + (pB.x + pB.y) + (pB.z + pB.w);
                *(float4*)(pdst)      = pA;
                *(float4*)(pdst + 32) = pB;
            }
        }

        // ================= PV phase: 4 sub-chunks of 256 k =================
        for (int vc = 0; vc < 4; ++vc) {
            __syncthreads();   // Kt/V readers done; p stores visible
            // stage V[256][64] naturally
            {
                const float4* vsrc = (const float4*)(Vg + ((size_t)bh * S_LEN + kbase + vc * 256) * D_KDIM);
                float4* vdst = (float4*)KV;
#pragma unroll
                for (int i = 0; i < 8; ++i) vdst[t + i * THREADS] = vsrc[t + i * THREADS];
            }
            __syncthreads();
            // warp w covers klocal in [w*16, w*16+16)
            const int dw = kg * 4;   // this thread's d base (dg == kg)
#pragma unroll 4
            for (int ki = 0; ki < 16; ++ki) {
                int klocal = w * 16 + ki;
                int kglob  = kbase + vc * 256 + klocal;
                float4 va = *(const float4*)(KV + klocal * D_KDIM + dw);
                float4 vb = *(const float4*)(KV + klocal * D_KDIM + dw + 32);
                ull v01 = pk(va.x, va.y), v23 = pk(va.z, va.w);
                ull v45 = pk(vb.x, vb.y), v67 = pk(vb.z, vb.w);
#pragma unroll
                for (int q = 0; q < 4; ++q) {
                    float p = Ps[(qg * 4 + q) * P_STRIDE + kglob];
                    ull pp = pk(p, p);
                    fma2(ctx[q][0], pp, v01);
                    fma2(ctx[q][1], pp, v23);
                    fma2(ctx[q][2], pp, v45);
                    fma2(ctx[q][3], pp, v67);
                }
            }
        }
    }

    // ================= row-sum reduction =================
#pragma unroll
    for (int q = 0; q < 4; ++q) {
        float v = lsum[q];
        v += __shfl_xor_sync(0xffffffffu, v, 1);
        v += __shfl_xor_sync(0xffffffffu, v, 2);
        v += __shfl_xor_sync(0xffffffffu, v, 4);
        if (kg == 0) Sred[w * 16 + qg * 4 + q] = v;
    }
    __syncthreads();
    if (t < 16) {
        float s = 0.f;
#pragma unroll
        for (int ww = 0; ww < 16; ++ww) s += Sred[ww * 16 + t];
        Sums[t] = 1.0f / s;
    }
    __syncthreads();   // last PV readers done; Sums not yet needed

    // ================= ctx partial write + cross-warp reduce =================
    {
        float* buf = KV;   // 16 warps x 1024 floats
#pragma unroll
        for (int q = 0; q < 4; ++q) {
            int o = (qg * 4 + q) * D_KDIM + kg * 4;
            float4 a, b;
            a.x = plo(ctx[q][0]); a.y = phi(ctx[q][0]);
            a.z = plo(ctx[q][1]); a.w = phi(ctx[q][1]);
            b.x = plo(ctx[q][2]); b.y = phi(ctx[q][2]);
            b.z = plo(ctx[q][3]); b.w = phi(ctx[q][3]);
            *(float4*)(buf + w * 1024 + o)      = a;
            *(float4*)(buf + w * 1024 + o + 32) = b;
        }
    }
    __syncthreads();
    {
#pragma unroll
        for (int rr = 0; rr < 2; ++rr) {
            int o = t + rr * THREADS;
            float s = 0.f;
#pragma unroll
            for (int ww = 0; ww < 16; ++ww) s += KV[ww * 1024 + o];
            int q = o >> 6, d = o & 63;
            ctx_out[(row0 + q) * D_KDIM + d] = s * Sums[q];
        }
    }

    // ================= weights write (normalized) =================
    {
#pragma unroll
        for (int it = 0; it < 16; ++it) {
            int i  = t + it * THREADS;      // float4 index 0..8191
            int q  = i >> 9;
            int k4 = i & 511;
            float inv = Sums[q];
            float4 p4 = *(const float4*)(Ps + q * P_STRIDE + k4 * 4);
            p4.x *= inv; p4.y *= inv; p4.z *= inv; p4.w *= inv;
            *(float4*)(w_out + (row0 + q) * (size_t)S_LEN + k4 * 4) = p4;
        }
    }
}

extern "C" void kernel_launch(void* const* d_in, const int* in_sizes, int n_in,
                              void* d_out, int out_size)
{
    const float*         Q = (const float*)d_in[0];
    const float*         K = (const float*)d_in[1];
    const float*         V = (const float*)d_in[2];
    const unsigned char* M = (const unsigned char*)d_in[3];

    float* ctx = (float*)d_out;
    float* wts = (float*)d_out + (size_t)BH * S_LEN * D_KDIM;

    cudaFuncSetAttribute(sdpa_fused_kernel,
                         cudaFuncAttributeMaxDynamicSharedMemorySize, SMEM_BYTES);

    detect_mask_kind_kernel<<<1, 256>>>((const unsigned*)M);

    dim3 grid(S_LEN / MQ, BH);   // (128, 32)
    sdpa_fused_kernel<<<grid, THREADS, SMEM_BYTES>>>(Q, K, V, M, ctx, wts);
}

// round 5
// speedup vs baseline: 5.1234x; 2.3656x over previous
#include <cuda_runtime.h>
#include <cuda_bf16.h>
#include <cstdint>
#include <cstddef>

#define S_LEN   2048
#define DKD     64
#define BHN     32
#define MQT     128          // q rows per CTA
#define NKC     128          // k cols per chunk
#define NCH     (S_LEN / NKC)
#define THREADS 512
#define STRB    144          // padded bf16 tile row stride in bytes (72 elems)

// ---- smem byte offsets ----
#define O_QHI 0
#define O_QLO 18432
#define O_KHI 36864
#define O_KLO 55296
#define O_VHI 73728
#define O_VLO 92160
#define O_RAW 110592         // 3 x 32768 rotating raw fp32 chunk buffers
#define O_RED 208896         // 128 floats
#define O_INV 209408         // 128 floats
#define SMEMB 209920

__device__ int g_mask_wide;

// ---------------- helpers ----------------
__device__ __forceinline__ uint32_t smem_u32(const void* p) {
    uint32_t a;
    asm("{ .reg .u64 t; cvta.to.shared.u64 t, %1; cvt.u32.u64 %0, t; }" : "=r"(a) : "l"(p));
    return a;
}
__device__ __forceinline__ uint32_t pkbf(float lo, float hi) {  // lo -> bits[15:0]
    uint32_t r; asm("cvt.rn.bf16x2.f32 %0, %1, %2;" : "=r"(r) : "f"(hi), "f"(lo)); return r;
}
__device__ __forceinline__ void ldsm4(uint32_t a, uint32_t& r0, uint32_t& r1, uint32_t& r2, uint32_t& r3) {
    asm volatile("ldmatrix.sync.aligned.m8n8.x4.shared.b16 {%0,%1,%2,%3}, [%4];"
                 : "=r"(r0), "=r"(r1), "=r"(r2), "=r"(r3) : "r"(a));
}
__device__ __forceinline__ void ldsm4t(uint32_t a, uint32_t& r0, uint32_t& r1, uint32_t& r2, uint32_t& r3) {
    asm volatile("ldmatrix.sync.aligned.m8n8.x4.trans.shared.b16 {%0,%1,%2,%3}, [%4];"
                 : "=r"(r0), "=r"(r1), "=r"(r2), "=r"(r3) : "r"(a));
}
__device__ __forceinline__ void mma16816(float* c, const uint32_t* A, uint32_t b0, uint32_t b1) {
    asm volatile("mma.sync.aligned.m16n8k16.row.col.f32.bf16.bf16.f32 "
                 "{%0,%1,%2,%3}, {%4,%5,%6,%7}, {%8,%9}, {%0,%1,%2,%3};"
                 : "+f"(c[0]), "+f"(c[1]), "+f"(c[2]), "+f"(c[3])
                 : "r"(A[0]), "r"(A[1]), "r"(A[2]), "r"(A[3]), "r"(b0), "r"(b1));
}
#define CP16(dst, src) asm volatile("cp.async.cg.shared.global [%0], [%1], 16;" :: "r"(dst), "l"(src))
#define CPCOMMIT()     asm volatile("cp.async.commit_group;" ::: "memory")
#define CPWAIT1()      asm volatile("cp.async.wait_group 1;" ::: "memory")

// split fp32 -> bf16 hi + bf16 residual(lo)
__device__ __forceinline__ void split2(float x0, float x1, uint32_t& hi, uint32_t& lo) {
    __nv_bfloat16 b0 = __float2bfloat16(x0), b1 = __float2bfloat16(x1);
    hi = (uint32_t)__bfloat16_as_ushort(b0) | ((uint32_t)__bfloat16_as_ushort(b1) << 16);
    lo = pkbf(x0 - __bfloat162float(b0), x1 - __bfloat162float(b1));
}

__global__ void detect_mask_kind_kernel(const unsigned* __restrict__ mw) {
    __shared__ int s_i32bad, s_f32bad;
    if (threadIdx.x == 0) { s_i32bad = 0; s_f32bad = 0; }
    __syncthreads();
    for (int i = threadIdx.x; i < 1024; i += blockDim.x) {
        unsigned w = mw[i];
        if (w > 1u)                      atomicOr(&s_i32bad, 1);
        if (w != 0u && w != 0x3F800000u) atomicOr(&s_f32bad, 1);
    }
    __syncthreads();
    if (threadIdx.x == 0) g_mask_wide = (!s_i32bad || !s_f32bad) ? 1 : 0;
}

__global__ void __launch_bounds__(THREADS, 1)
sdpa_mma_kernel(const float* __restrict__ Qg,
                const float* __restrict__ Kg,
                const float* __restrict__ Vg,
                const unsigned char* __restrict__ Mg,
                float* __restrict__ ctx_out,
                float* __restrict__ w_out)
{
    extern __shared__ char smem[];
    const uint32_t sb = smem_u32(smem);

    const int t    = threadIdx.x;
    const int lane = t & 31;
    const int w    = t >> 5;
    const int wr   = w & 7;        // warp-row: q rows wr*16..+15
    const int wc   = w >> 3;       // warp-col: k half (0/1)
    const int tq   = lane >> 2;    // 0..7
    const int tc   = lane & 3;     // 0..3

    const int bh = blockIdx.y;
    const int q0 = blockIdx.x * MQT;
    const size_t row0 = (size_t)bh * S_LEN + q0;
    const int wide = g_mask_wide;

    float* red  = (float*)(smem + O_RED);
    float* sinv = (float*)(smem + O_INV);

    const float* Kbh = Kg + (size_t)bh * S_LEN * DKD;
    const float* Vbh = Vg + (size_t)bh * S_LEN * DKD;

    // this thread's two q rows (frag rows r and r+8)
    const size_t qrA = row0 + wr * 16 + tq;
    const size_t qrB = qrA + 8;
    const size_t mrowA = qrA * (size_t)S_LEN;
    const size_t mrowB = qrB * (size_t)S_LEN;

    // ---- prologue: prefetch K0, V0 raw; stage Q bf16 hi/lo (scaled 1/8) ----
    {
        const char* src = (const char*)Kbh;
#pragma unroll
        for (int kk = 0; kk < 4; ++kk) {
            int i = t + kk * THREADS;
            CP16(sb + O_RAW + i * 16, src + (size_t)i * 16);
        }
        CPCOMMIT();
        src = (const char*)Vbh;
#pragma unroll
        for (int kk = 0; kk < 4; ++kk) {
            int i = t + kk * THREADS;
            CP16(sb + O_RAW + 32768 + i * 16, src + (size_t)i * 16);
        }
        CPCOMMIT();
        // Q staging
        const float4* q4 = (const float4*)(Qg + row0 * DKD);
#pragma unroll
        for (int kk = 0; kk < 4; ++kk) {
            int i = t + kk * THREADS;
            int row = i >> 4, c4 = i & 15;
            float4 v = q4[i];
            v.x *= 0.125f; v.y *= 0.125f; v.z *= 0.125f; v.w *= 0.125f;
            uint2 H, L;
            split2(v.x, v.y, H.x, L.x);
            split2(v.z, v.w, H.y, L.y);
            *(uint2*)(smem + O_QHI + row * STRB + c4 * 8) = H;
            *(uint2*)(smem + O_QLO + row * STRB + c4 * 8) = L;
        }
    }

    float ctx[8][4] = {};
    float rs0 = 0.f, rs1 = 0.f;

    for (int ch = 0; ch < NCH; ++ch) {
        const int kb = ch * NKC;
        const uint32_t rawK = sb + O_RAW + ((2 * ch) % 3) * 32768;
        const uint32_t rawV = sb + O_RAW + ((2 * ch + 1) % 3) * 32768;

        // ---- K chunk raw ready -> convert to bf16 hi/lo ----
        CPWAIT1();
        __syncthreads();
        {
            const float4* rb = (const float4*)(smem + (rawK - sb));
#pragma unroll
            for (int kk = 0; kk < 4; ++kk) {
                int i = t + kk * THREADS;
                int row = i >> 4, c4 = i & 15;
                float4 v = rb[i];
                uint2 H, L;
                split2(v.x, v.y, H.x, L.x);
                split2(v.z, v.w, H.y, L.y);
                *(uint2*)(smem + O_KHI + row * STRB + c4 * 8) = H;
                *(uint2*)(smem + O_KLO + row * STRB + c4 * 8) = L;
            }
        }
        __syncthreads();
        if (ch < NCH - 1) {   // prefetch K_{ch+1}
            const char* src = (const char*)(Kbh + (size_t)(kb + NKC) * DKD);
            uint32_t dst = sb + O_RAW + ((2 * ch + 2) % 3) * 32768;
#pragma unroll
            for (int kk = 0; kk < 4; ++kk) {
                int i = t + kk * THREADS;
                CP16(dst + i * 16, src + (size_t)i * 16);
            }
            CPCOMMIT();
        }

        // ---- mask bits for this thread's 8 frags (4 bits each) ----
        uint32_t mk = 0;
#pragma unroll
        for (int j = 0; j < 8; ++j) {
            int col = kb + wc * 64 + j * 8 + 2 * tc;
            uint32_t b0, b1, b2, b3;
            if (wide) {
                uint2 a = *(const uint2*)((const unsigned*)Mg + mrowA + col);
                uint2 b = *(const uint2*)((const unsigned*)Mg + mrowB + col);
                b0 = a.x != 0u; b1 = a.y != 0u; b2 = b.x != 0u; b3 = b.y != 0u;
            } else {
                unsigned short a = *(const unsigned short*)(Mg + mrowA + col);
                unsigned short b = *(const unsigned short*)(Mg + mrowB + col);
                b0 = a & 0xFF; b1 = a >> 8; b2 = b & 0xFF; b3 = b >> 8;
                b0 = b0 != 0; b1 = b1 != 0; b2 = b2 != 0; b3 = b3 != 0;
            }
            mk |= (b0 << (4 * j)) | (b1 << (4 * j + 1)) | (b2 << (4 * j + 2)) | (b3 << (4 * j + 3));
        }

        // ---- S phase: 3 product passes ----
        float acc[8][4] = {};
        uint32_t QA[4][4];
#pragma unroll
        for (int pass = 0; pass < 3; ++pass) {
            const uint32_t qb = (pass == 2) ? (sb + O_QLO) : (sb + O_QHI);
            const uint32_t kbuf = (pass == 1) ? (sb + O_KLO) : (sb + O_KHI);
            if (pass != 1) {   // (re)load A frags
#pragma unroll
                for (int s = 0; s < 4; ++s) {
                    uint32_t a = qb + (wr * 16 + (lane & 15)) * STRB + (s * 16 + (lane >> 4) * 8) * 2;
                    ldsm4(a, QA[s][0], QA[s][1], QA[s][2], QA[s][3]);
                }
            }
#pragma unroll
            for (int j = 0; j < 8; ++j) {
#pragma unroll
                for (int sp = 0; sp < 4; sp += 2) {
                    uint32_t b0, b1, b2, b3;
                    uint32_t a = kbuf + (wc * 64 + j * 8 + (lane & 7)) * STRB
                               + (sp * 16 + (lane >> 3) * 8) * 2;
                    ldsm4(a, b0, b1, b2, b3);
                    mma16816(acc[j], QA[sp], b0, b1);
                    mma16816(acc[j], QA[sp + 1], b2, b3);
                }
            }
        }

        // ---- mask + exp + rowsum + unnormalized weight store ----
#pragma unroll
        for (int j = 0; j < 8; ++j) {
            float e0 = ((mk >> (4 * j)) & 1u)     ? 0.f : __expf(acc[j][0]);
            float e1 = ((mk >> (4 * j + 1)) & 1u) ? 0.f : __expf(acc[j][1]);
            float e2 = ((mk >> (4 * j + 2)) & 1u) ? 0.f : __expf(acc[j][2]);
            float e3 = ((mk >> (4 * j + 3)) & 1u) ? 0.f : __expf(acc[j][3]);
            rs0 += e0 + e1;  rs1 += e2 + e3;
            int col = kb + wc * 64 + j * 8 + 2 * tc;
            *(float2*)(w_out + mrowA + col) = make_float2(e0, e1);
            *(float2*)(w_out + mrowB + col) = make_float2(e2, e3);
            acc[j][0] = e0; acc[j][1] = e1; acc[j][2] = e2; acc[j][3] = e3;
        }

        // ---- repack P as bf16 hi/lo A-frags (D layout == half A layout) ----
        uint32_t PAh[4][4], PAl[4][4];
#pragma unroll
        for (int s = 0; s < 4; ++s) {
            split2(acc[2 * s][0],     acc[2 * s][1],     PAh[s][0], PAl[s][0]);
            split2(acc[2 * s][2],     acc[2 * s][3],     PAh[s][1], PAl[s][1]);
            split2(acc[2 * s + 1][0], acc[2 * s + 1][1], PAh[s][2], PAl[s][2]);
            split2(acc[2 * s + 1][2], acc[2 * s + 1][3], PAh[s][3], PAl[s][3]);
        }

        // ---- V chunk raw ready -> convert ----
        CPWAIT1();
        __syncthreads();
        {
            const float4* rb = (const float4*)(smem + (rawV - sb));
#pragma unroll
            for (int kk = 0; kk < 4; ++kk) {
                int i = t + kk * THREADS;
                int row = i >> 4, c4 = i & 15;
                float4 v = rb[i];
                uint2 H, L;
                split2(v.x, v.y, H.x, L.x);
                split2(v.z, v.w, H.y, L.y);
                *(uint2*)(smem + O_VHI + row * STRB + c4 * 8) = H;
                *(uint2*)(smem + O_VLO + row * STRB + c4 * 8) = L;
            }
        }
        __syncthreads();
        if (ch < NCH - 1) {   // prefetch V_{ch+1}
            const char* src = (const char*)(Vbh + (size_t)(kb + NKC) * DKD);
            uint32_t dst = sb + O_RAW + ((2 * ch + 3) % 3) * 32768;
#pragma unroll
            for (int kk = 0; kk < 4; ++kk) {
                int i = t + kk * THREADS;
                CP16(dst + i * 16, src + (size_t)i * 16);
            }
            CPCOMMIT();
        }

        // ---- PV phase ----
#pragma unroll
        for (int s = 0; s < 4; ++s) {
#pragma unroll
            for (int j2 = 0; j2 < 4; ++j2) {
                uint32_t vrow = (wc * 64 + s * 16 + (lane & 15));
                uint32_t vcol = (j2 * 16 + (lane >> 4) * 8) * 2;
                uint32_t bh0, bh1, bh2, bh3, bl0, bl1, bl2, bl3;
                ldsm4t(sb + O_VHI + vrow * STRB + vcol, bh0, bh1, bh2, bh3);
                ldsm4t(sb + O_VLO + vrow * STRB + vcol, bl0, bl1, bl2, bl3);
                mma16816(ctx[2 * j2],     PAh[s], bh0, bh1);
                mma16816(ctx[2 * j2],     PAl[s], bh0, bh1);
                mma16816(ctx[2 * j2],     PAh[s], bl0, bl1);
                mma16816(ctx[2 * j2 + 1], PAh[s], bh2, bh3);
                mma16816(ctx[2 * j2 + 1], PAl[s], bh2, bh3);
                mma16816(ctx[2 * j2 + 1], PAh[s], bl2, bl3);
            }
        }
    }

    // ================= row-sum reduction =================
    __syncthreads();
    if (t < 128) red[t] = 0.f;
    __syncthreads();
    rs0 += __shfl_xor_sync(0xffffffffu, rs0, 1);
    rs0 += __shfl_xor_sync(0xffffffffu, rs0, 2);
    rs1 += __shfl_xor_sync(0xffffffffu, rs1, 1);
    rs1 += __shfl_xor_sync(0xffffffffu, rs1, 2);
    if (tc == 0) {
        atomicAdd(&red[wr * 16 + tq], rs0);
        atomicAdd(&red[wr * 16 + tq + 8], rs1);
    }
    // ctx partials -> smem (reuse raw buffers; all cp.async drained)
    {
        float* cbuf = (float*)(smem + O_RAW + wc * 32768);
#pragma unroll
        for (int j = 0; j < 8; ++j) {
            int row = wr * 16 + tq, col = j * 8 + 2 * tc;
            *(float2*)(cbuf + row * 64 + col)       = make_float2(ctx[j][0], ctx[j][1]);
            *(float2*)(cbuf + (row + 8) * 64 + col) = make_float2(ctx[j][2], ctx[j][3]);
        }
    }
    __syncthreads();
    if (t < 128) sinv[t] = 1.0f / red[t];
    __syncthreads();

    // ================= ctx combine + write =================
    {
        const float4* b0 = (const float4*)(smem + O_RAW);
        const float4* b1 = (const float4*)(smem + O_RAW + 32768);
#pragma unroll
        for (int kk = 0; kk < 4; ++kk) {
            int i = t + kk * THREADS;
            int row = i >> 4, c4 = i & 15;
            float4 a = b0[i], b = b1[i];
            float iv = sinv[row];
            float4 o;
            o.x = (a.x + b.x) * iv; o.y = (a.y + b.y) * iv;
            o.z = (a.z + b.z) * iv; o.w = (a.w + b.w) * iv;
            *(float4*)(ctx_out + (row0 + row) * DKD + c4 * 4) = o;
        }
    }

    // ================= weights normalization (in-place rescale) =================
#pragma unroll 1
    for (int r = 0; r < MQT; r += 4) {
        float4 v0 = ((float4*)(w_out + (row0 + r)     * (size_t)S_LEN))[t];
        float4 v1 = ((float4*)(w_out + (row0 + r + 1) * (size_t)S_LEN))[t];
        float4 v2 = ((float4*)(w_out + (row0 + r + 2) * (size_t)S_LEN))[t];
        float4 v3 = ((float4*)(w_out + (row0 + r + 3) * (size_t)S_LEN))[t];
        float i0 = sinv[r], i1 = sinv[r + 1], i2 = sinv[r + 2], i3 = sinv[r + 3];
        v0.x *= i0; v0.y *= i0; v0.z *= i0; v0.w *= i0;
        v1.x *= i1; v1.y *= i1; v1.z *= i1; v1.w *= i1;
        v2.x *= i2; v2.y *= i2; v2.z *= i2; v2.w *= i2;
        v3.x *= i3; v3.y *= i3; v3.z *= i3; v3.w *= i3;
        ((float4*)(w_out + (row0 + r)     * (size_t)S_LEN))[t] = v0;
        ((float4*)(w_out + (row0 + r + 1) * (size_t)S_LEN))[t] = v1;
        ((float4*)(w_out + (row0 + r + 2) * (size_t)S_LEN))[t] = v2;
        ((float4*)(w_out + (row0 + r + 3) * (size_t)S_LEN))[t] = v3;
    }
}

extern "C" void kernel_launch(void* const* d_in, const int* in_sizes, int n_in,
                              void* d_out, int out_size)
{
    const float*         Q = (const float*)d_in[0];
    const float*         K = (const float*)d_in[1];
    const float*         V = (const float*)d_in[2];
    const unsigned char* M = (const unsigned char*)d_in[3];

    float* ctx = (float*)d_out;
    float* wts = (float*)d_out + (size_t)BHN * S_LEN * DKD;

    cudaFuncSetAttribute(sdpa_mma_kernel,
                         cudaFuncAttributeMaxDynamicSharedMemorySize, SMEMB);

    detect_mask_kind_kernel<<<1, 256>>>((const unsigned*)M);

    dim3 grid(S_LEN / MQT, BHN);   // (16, 32) = 512 CTAs
    sdpa_mma_kernel<<<grid, THREADS, SMEMB>>>(Q, K, V, M, ctx, wts);
}

// round 6
// speedup vs baseline: 5.5833x; 1.0898x over previous
#include <cuda_runtime.h>
#include <cuda_bf16.h>
#include <cstdint>
#include <cstddef>

#define S_LEN   2048
#define DKD     64
#define BHN     32
#define MQT     128          // q rows per CTA
#define NKC     128          // k cols per chunk
#define NCH     (S_LEN / NKC)
#define THREADS 512
#define STRB    144          // padded bf16 tile row stride in bytes (72 elems)

// ---- smem byte offsets ----
#define O_QHI 0
#define O_QLO 18432
#define O_KHI 36864
#define O_KLO 55296
#define O_VHI 73728
#define O_VLO 92160
#define O_RAW 110592         // 2 x 32768 raw fp32 staging buffers (K, V)
#define O_MC  176128         // mask bit cache: 16 chunks x 512 threads x 4B = 32KB
#define O_RED 208896         // 128 floats
#define O_INV 209408         // 128 floats
#define SMEMB 209920

__device__ int g_mask_wide;

// ---------------- helpers ----------------
__device__ __forceinline__ uint32_t smem_u32(const void* p) {
    uint32_t a;
    asm("{ .reg .u64 t; cvta.to.shared.u64 t, %1; cvt.u32.u64 %0, t; }" : "=r"(a) : "l"(p));
    return a;
}
__device__ __forceinline__ uint32_t pkbf(float lo, float hi) {  // lo -> bits[15:0]
    uint32_t r; asm("cvt.rn.bf16x2.f32 %0, %1, %2;" : "=r"(r) : "f"(hi), "f"(lo)); return r;
}
__device__ __forceinline__ void ldsm4(uint32_t a, uint32_t& r0, uint32_t& r1, uint32_t& r2, uint32_t& r3) {
    asm volatile("ldmatrix.sync.aligned.m8n8.x4.shared.b16 {%0,%1,%2,%3}, [%4];"
                 : "=r"(r0), "=r"(r1), "=r"(r2), "=r"(r3) : "r"(a));
}
__device__ __forceinline__ void ldsm4t(uint32_t a, uint32_t& r0, uint32_t& r1, uint32_t& r2, uint32_t& r3) {
    asm volatile("ldmatrix.sync.aligned.m8n8.x4.trans.shared.b16 {%0,%1,%2,%3}, [%4];"
                 : "=r"(r0), "=r"(r1), "=r"(r2), "=r"(r3) : "r"(a));
}
__device__ __forceinline__ void mma16816(float* c, const uint32_t* A, uint32_t b0, uint32_t b1) {
    asm volatile("mma.sync.aligned.m16n8k16.row.col.f32.bf16.bf16.f32 "
                 "{%0,%1,%2,%3}, {%4,%5,%6,%7}, {%8,%9}, {%0,%1,%2,%3};"
                 : "+f"(c[0]), "+f"(c[1]), "+f"(c[2]), "+f"(c[3])
                 : "r"(A[0]), "r"(A[1]), "r"(A[2]), "r"(A[3]), "r"(b0), "r"(b1));
}
#define CP16(dst, src) asm volatile("cp.async.cg.shared.global [%0], [%1], 16;" :: "r"(dst), "l"(src))
#define CPCOMMIT()     asm volatile("cp.async.commit_group;" ::: "memory")
#define CPWAIT1()      asm volatile("cp.async.wait_group 1;" ::: "memory")
#define CPWAIT0()      asm volatile("cp.async.wait_group 0;" ::: "memory")

// split fp32 -> bf16 hi + bf16 residual(lo)
__device__ __forceinline__ void split2(float x0, float x1, uint32_t& hi, uint32_t& lo) {
    __nv_bfloat16 b0 = __float2bfloat16(x0), b1 = __float2bfloat16(x1);
    hi = (uint32_t)__bfloat16_as_ushort(b0) | ((uint32_t)__bfloat16_as_ushort(b1) << 16);
    lo = pkbf(x0 - __bfloat162float(b0), x1 - __bfloat162float(b1));
}

// convert a raw fp32 [128x64] chunk in smem -> bf16 hi/lo padded tiles
__device__ __forceinline__ void convert_chunk(const char* smem, uint32_t rawOff,
                                              char* hiBuf, char* loBuf, int t, float scale) {
    const float4* rb = (const float4*)(smem + rawOff);
#pragma unroll
    for (int kk = 0; kk < 4; ++kk) {
        int i = t + kk * THREADS;
        int row = i >> 4, c4 = i & 15;
        float4 v = rb[i];
        v.x *= scale; v.y *= scale; v.z *= scale; v.w *= scale;
        uint2 H, L;
        split2(v.x, v.y, H.x, L.x);
        split2(v.z, v.w, H.y, L.y);
        *(uint2*)(hiBuf + row * STRB + c4 * 8) = H;
        *(uint2*)(loBuf + row * STRB + c4 * 8) = L;
    }
}

// issue a 32KB chunk prefetch (128x64 fp32)
__device__ __forceinline__ void prefetch_chunk(uint32_t dst, const float* src, int t) {
    const char* s = (const char*)src;
#pragma unroll
    for (int kk = 0; kk < 4; ++kk) {
        int i = t + kk * THREADS;
        CP16(dst + i * 16, s + (size_t)i * 16);
    }
    CPCOMMIT();
}

// S phase: acc += 3-product split GEMM on Q(hi/lo) x K(hi/lo)
__device__ __forceinline__ void s_phase(uint32_t sb, uint32_t khi, uint32_t klo,
                                        float acc[8][4], int lane, int wr, int wc) {
    uint32_t QA[4][4];
#pragma unroll
    for (int pass = 0; pass < 3; ++pass) {
        const uint32_t qb = (pass == 2) ? (sb + O_QLO) : (sb + O_QHI);
        const uint32_t kbuf = (pass == 1) ? klo : khi;
        if (pass != 1) {
#pragma unroll
            for (int s = 0; s < 4; ++s) {
                uint32_t a = qb + (wr * 16 + (lane & 15)) * STRB + (s * 16 + (lane >> 4) * 8) * 2;
                ldsm4(a, QA[s][0], QA[s][1], QA[s][2], QA[s][3]);
            }
        }
#pragma unroll
        for (int j = 0; j < 8; ++j) {
#pragma unroll
            for (int sp = 0; sp < 4; sp += 2) {
                uint32_t b0, b1, b2, b3;
                uint32_t a = kbuf + (wc * 64 + j * 8 + (lane & 7)) * STRB
                           + (sp * 16 + (lane >> 3) * 8) * 2;
                ldsm4(a, b0, b1, b2, b3);
                mma16816(acc[j], QA[sp], b0, b1);
                mma16816(acc[j], QA[sp + 1], b2, b3);
            }
        }
    }
}

__global__ void detect_mask_kind_kernel(const unsigned* __restrict__ mw) {
    __shared__ int s_i32bad, s_f32bad;
    if (threadIdx.x == 0) { s_i32bad = 0; s_f32bad = 0; }
    __syncthreads();
    for (int i = threadIdx.x; i < 1024; i += blockDim.x) {
        unsigned w = mw[i];
        if (w > 1u)                      atomicOr(&s_i32bad, 1);
        if (w != 0u && w != 0x3F800000u) atomicOr(&s_f32bad, 1);
    }
    __syncthreads();
    if (threadIdx.x == 0) g_mask_wide = (!s_i32bad || !s_f32bad) ? 1 : 0;
}

__global__ void __launch_bounds__(THREADS, 1)
sdpa_mma_kernel(const float* __restrict__ Qg,
                const float* __restrict__ Kg,
                const float* __restrict__ Vg,
                const unsigned char* __restrict__ Mg,
                float* __restrict__ ctx_out,
                float* __restrict__ w_out)
{
    extern __shared__ char smem[];
    const uint32_t sb = smem_u32(smem);

    const int t    = threadIdx.x;
    const int lane = t & 31;
    const int w    = t >> 5;
    const int wr   = w & 7;        // warp-row: q rows wr*16..+15
    const int wc   = w >> 3;       // warp-col: k half (0/1)
    const int tq   = lane >> 2;    // 0..7
    const int tc   = lane & 3;     // 0..3

    const int bh = blockIdx.y;
    const int q0 = blockIdx.x * MQT;
    const size_t row0 = (size_t)bh * S_LEN + q0;
    const int wide = g_mask_wide;

    float*     red    = (float*)(smem + O_RED);
    float*     sinv   = (float*)(smem + O_INV);
    uint32_t*  mcache = (uint32_t*)(smem + O_MC);

    const float* Kbh = Kg + (size_t)bh * S_LEN * DKD;
    const float* Vbh = Vg + (size_t)bh * S_LEN * DKD;

    const size_t qrA = row0 + wr * 16 + tq;
    const size_t qrB = qrA + 8;
    const size_t mrowA = qrA * (size_t)S_LEN;
    const size_t mrowB = qrB * (size_t)S_LEN;

    const uint32_t rawK = sb + O_RAW;
    const uint32_t rawV = sb + O_RAW + 32768;

    // ---- prologue: prefetch K0, V0 raw; stage Q bf16 hi/lo (scaled 1/8) ----
    prefetch_chunk(rawK, Kbh, t);
    prefetch_chunk(rawV, Vbh, t);
    {
        const float4* q4 = (const float4*)(Qg + row0 * DKD);
#pragma unroll
        for (int kk = 0; kk < 4; ++kk) {
            int i = t + kk * THREADS;
            int row = i >> 4, c4 = i & 15;
            float4 v = q4[i];
            v.x *= 0.125f; v.y *= 0.125f; v.z *= 0.125f; v.w *= 0.125f;
            uint2 H, L;
            split2(v.x, v.y, H.x, L.x);
            split2(v.z, v.w, H.y, L.y);
            *(uint2*)(smem + O_QHI + row * STRB + c4 * 8) = H;
            *(uint2*)(smem + O_QLO + row * STRB + c4 * 8) = L;
        }
    }

    float ctx[8][4] = {};
    float rs0 = 0.f, rs1 = 0.f;

    // ================== PASS 1: S + exp + rowsum + PV (no weight writes) ==================
    for (int ch = 0; ch < NCH; ++ch) {
        const int kb = ch * NKC;

        // K raw ready -> convert
        CPWAIT1();
        __syncthreads();
        convert_chunk(smem, O_RAW, smem + O_KHI, smem + O_KLO, t, 1.0f);
        __syncthreads();
        if (ch < NCH - 1) prefetch_chunk(rawK, Kbh + (size_t)(kb + NKC) * DKD, t);

        // mask bits (gather from gmem, cache to smem for pass 2)
        uint32_t mk = 0;
#pragma unroll
        for (int j = 0; j < 8; ++j) {
            int col = kb + wc * 64 + j * 8 + 2 * tc;
            uint32_t b0, b1, b2, b3;
            if (wide) {
                uint2 a = *(const uint2*)((const unsigned*)Mg + mrowA + col);
                uint2 b = *(const uint2*)((const unsigned*)Mg + mrowB + col);
                b0 = a.x != 0u; b1 = a.y != 0u; b2 = b.x != 0u; b3 = b.y != 0u;
            } else {
                unsigned short a = *(const unsigned short*)(Mg + mrowA + col);
                unsigned short b = *(const unsigned short*)(Mg + mrowB + col);
                b0 = (a & 0xFF) != 0; b1 = (a >> 8) != 0;
                b2 = (b & 0xFF) != 0; b3 = (b >> 8) != 0;
            }
            mk |= (b0 << (4 * j)) | (b1 << (4 * j + 1)) | (b2 << (4 * j + 2)) | (b3 << (4 * j + 3));
        }
        mcache[ch * THREADS + t] = mk;

        // S phase
        float acc[8][4] = {};
        s_phase(sb, sb + O_KHI, sb + O_KLO, acc, lane, wr, wc);

        // mask + exp + rowsum (keep unnormalized p in acc)
#pragma unroll
        for (int j = 0; j < 8; ++j) {
            float e0 = ((mk >> (4 * j)) & 1u)     ? 0.f : __expf(acc[j][0]);
            float e1 = ((mk >> (4 * j + 1)) & 1u) ? 0.f : __expf(acc[j][1]);
            float e2 = ((mk >> (4 * j + 2)) & 1u) ? 0.f : __expf(acc[j][2]);
            float e3 = ((mk >> (4 * j + 3)) & 1u) ? 0.f : __expf(acc[j][3]);
            rs0 += e0 + e1;  rs1 += e2 + e3;
            acc[j][0] = e0; acc[j][1] = e1; acc[j][2] = e2; acc[j][3] = e3;
        }

        // repack P as bf16 hi/lo A-frags
        uint32_t PAh[4][4], PAl[4][4];
#pragma unroll
        for (int s = 0; s < 4; ++s) {
            split2(acc[2 * s][0],     acc[2 * s][1],     PAh[s][0], PAl[s][0]);
            split2(acc[2 * s][2],     acc[2 * s][3],     PAh[s][1], PAl[s][1]);
            split2(acc[2 * s + 1][0], acc[2 * s + 1][1], PAh[s][2], PAl[s][2]);
            split2(acc[2 * s + 1][2], acc[2 * s + 1][3], PAh[s][3], PAl[s][3]);
        }

        // V raw ready -> convert  (last chunk must wait fully: wait_group 0)
        if (ch < NCH - 1) { CPWAIT1(); } else { CPWAIT0(); }
        __syncthreads();
        convert_chunk(smem, O_RAW + 32768, smem + O_VHI, smem + O_VLO, t, 1.0f);
        __syncthreads();
        if (ch < NCH - 1) prefetch_chunk(rawV, Vbh + (size_t)(kb + NKC) * DKD, t);

        // PV phase
#pragma unroll
        for (int s = 0; s < 4; ++s) {
#pragma unroll
            for (int j2 = 0; j2 < 4; ++j2) {
                uint32_t vrow = (wc * 64 + s * 16 + (lane & 15));
                uint32_t vcol = (j2 * 16 + (lane >> 4) * 8) * 2;
                uint32_t bh0, bh1, bh2, bh3, bl0, bl1, bl2, bl3;
                ldsm4t(sb + O_VHI + vrow * STRB + vcol, bh0, bh1, bh2, bh3);
                ldsm4t(sb + O_VLO + vrow * STRB + vcol, bl0, bl1, bl2, bl3);
                mma16816(ctx[2 * j2],     PAh[s], bh0, bh1);
                mma16816(ctx[2 * j2],     PAl[s], bh0, bh1);
                mma16816(ctx[2 * j2],     PAh[s], bl0, bl1);
                mma16816(ctx[2 * j2 + 1], PAh[s], bh2, bh3);
                mma16816(ctx[2 * j2 + 1], PAl[s], bh2, bh3);
                mma16816(ctx[2 * j2 + 1], PAh[s], bl2, bl3);
            }
        }
    }

    // ---- pass-2 prefetch: K0 -> rawA, K1 -> rawB (raw buffers free now) ----
    prefetch_chunk(rawK, Kbh, t);
    prefetch_chunk(rawV, Kbh + (size_t)NKC * DKD, t);

    // ================= row-sum reduction =================
    __syncthreads();
    if (t < 128) red[t] = 0.f;
    __syncthreads();
    rs0 += __shfl_xor_sync(0xffffffffu, rs0, 1);
    rs0 += __shfl_xor_sync(0xffffffffu, rs0, 2);
    rs1 += __shfl_xor_sync(0xffffffffu, rs1, 1);
    rs1 += __shfl_xor_sync(0xffffffffu, rs1, 2);
    if (tc == 0) {
        atomicAdd(&red[wr * 16 + tq], rs0);
        atomicAdd(&red[wr * 16 + tq + 8], rs1);
    }
    // ctx partials into the (now dead) bf16 K/V tile region
    {
        float* cbuf = (float*)(smem + O_KHI) + wc * 8192;
#pragma unroll
        for (int j = 0; j < 8; ++j) {
            int row = wr * 16 + tq, col = j * 8 + 2 * tc;
            *(float2*)(cbuf + row * 64 + col)       = make_float2(ctx[j][0], ctx[j][1]);
            *(float2*)(cbuf + (row + 8) * 64 + col) = make_float2(ctx[j][2], ctx[j][3]);
        }
    }
    __syncthreads();
    if (t < 128) sinv[t] = 1.0f / red[t];
    __syncthreads();

    // ================= ctx combine + write =================
    {
        const float4* b0 = (const float4*)(smem + O_KHI);
        const float4* b1 = (const float4*)(smem + O_KHI) + 2048;
#pragma unroll
        for (int kk = 0; kk < 4; ++kk) {
            int i = t + kk * THREADS;
            int row = i >> 4, c4 = i & 15;
            float4 a = b0[i], b = b1[i];
            float iv = sinv[row];
            float4 o;
            o.x = (a.x + b.x) * iv; o.y = (a.y + b.y) * iv;
            o.z = (a.z + b.z) * iv; o.w = (a.w + b.w) * iv;
            *(float4*)(ctx_out + (row0 + row) * DKD + c4 * 4) = o;
        }
    }
    __syncthreads();

    // ================== PASS 2: recompute S, write normalized weights ==================
    const float ivA = sinv[wr * 16 + tq];
    const float ivB = sinv[wr * 16 + tq + 8];
    for (int ch = 0; ch < NCH; ++ch) {
        const int kb = ch * NKC;
        if (ch < NCH - 1) { CPWAIT1(); } else { CPWAIT0(); }
        __syncthreads();
        const uint32_t raw = (ch & 1) ? (O_RAW + 32768) : O_RAW;
        char* hiB = smem + ((ch & 1) ? O_VHI : O_KHI);
        char* loB = smem + ((ch & 1) ? O_VLO : O_KLO);
        convert_chunk(smem, raw, hiB, loB, t, 1.0f);
        __syncthreads();
        if (ch + 2 < NCH)
            prefetch_chunk(sb + raw, Kbh + (size_t)(kb + 2 * NKC) * DKD, t);

        float acc[8][4] = {};
        s_phase(sb, smem_u32(hiB), smem_u32(loB), acc, lane, wr, wc);

        const uint32_t mk = mcache[ch * THREADS + t];
#pragma unroll
        for (int j = 0; j < 8; ++j) {
            float e0 = ((mk >> (4 * j)) & 1u)     ? 0.f : __expf(acc[j][0]) * ivA;
            float e1 = ((mk >> (4 * j + 1)) & 1u) ? 0.f : __expf(acc[j][1]) * ivA;
            float e2 = ((mk >> (4 * j + 2)) & 1u) ? 0.f : __expf(acc[j][2]) * ivB;
            float e3 = ((mk >> (4 * j + 3)) & 1u) ? 0.f : __expf(acc[j][3]) * ivB;
            int col = kb + wc * 64 + j * 8 + 2 * tc;
            __stcs((float2*)(w_out + mrowA + col), make_float2(e0, e1));
            __stcs((float2*)(w_out + mrowB + col), make_float2(e2, e3));
        }
    }
}

extern "C" void kernel_launch(void* const* d_in, const int* in_sizes, int n_in,
                              void* d_out, int out_size)
{
    const float*         Q = (const float*)d_in[0];
    const float*         K = (const float*)d_in[1];
    const float*         V = (const float*)d_in[2];
    const unsigned char* M = (const unsigned char*)d_in[3];

    float* ctx = (float*)d_out;
    float* wts = (float*)d_out + (size_t)BHN * S_LEN * DKD;

    cudaFuncSetAttribute(sdpa_mma_kernel,
                         cudaFuncAttributeMaxDynamicSharedMemorySize, SMEMB);

    detect_mask_kind_kernel<<<1, 256>>>((const unsigned*)M);

    dim3 grid(S_LEN / MQT, BHN);   // (16, 32) = 512 CTAs
    sdpa_mma_kernel<<<grid, THREADS, SMEMB>>>(Q, K, V, M, ctx, wts);
}

// round 7
// speedup vs baseline: 5.9200x; 1.0603x over previous
#include <cuda_runtime.h>
#include <cuda_bf16.h>
#include <cstdint>
#include <cstddef>

#define S_LEN   2048
#define DKD     64
#define BHN     32
#define MQT     128          // q rows per CTA
#define NKC     128          // k cols per chunk
#define NCH     (S_LEN / NKC)
#define THREADS 512
#define STRB    144          // padded bf16 tile row stride in bytes (72 elems)

// ---- smem byte offsets ----
#define O_QHI 0
#define O_QLO 18432
#define O_KHI 36864
#define O_KLO 55296
#define O_VHI 73728
#define O_VLO 92160
#define O_RAW 110592         // 2 x 32768 raw fp32 staging buffers (K, V)
#define O_MC  176128         // mask bit cache: 16 chunks x 512 threads x 4B = 32KB
#define O_RED 208896         // 128 floats
#define O_INV 209408         // 128 floats
#define SMEMB 209920

// 0.125 * log2(e): fold softmax scale + exp->exp2 conversion into Q
#define QSCALE 0.1803368801111831f

__device__ int g_mask_wide;

// ---------------- helpers ----------------
__device__ __forceinline__ uint32_t smem_u32(const void* p) {
    uint32_t a;
    asm("{ .reg .u64 t; cvta.to.shared.u64 t, %1; cvt.u32.u64 %0, t; }" : "=r"(a) : "l"(p));
    return a;
}
__device__ __forceinline__ float ex2f(float x) {
    float y; asm("ex2.approx.f32 %0, %1;" : "=f"(y) : "f"(x)); return y;
}
__device__ __forceinline__ uint32_t pkbf(float lo, float hi) {  // lo -> bits[15:0]
    uint32_t r; asm("cvt.rn.bf16x2.f32 %0, %1, %2;" : "=r"(r) : "f"(hi), "f"(lo)); return r;
}
__device__ __forceinline__ void ldsm4(uint32_t a, uint32_t& r0, uint32_t& r1, uint32_t& r2, uint32_t& r3) {
    asm volatile("ldmatrix.sync.aligned.m8n8.x4.shared.b16 {%0,%1,%2,%3}, [%4];"
                 : "=r"(r0), "=r"(r1), "=r"(r2), "=r"(r3) : "r"(a));
}
__device__ __forceinline__ void ldsm4t(uint32_t a, uint32_t& r0, uint32_t& r1, uint32_t& r2, uint32_t& r3) {
    asm volatile("ldmatrix.sync.aligned.m8n8.x4.trans.shared.b16 {%0,%1,%2,%3}, [%4];"
                 : "=r"(r0), "=r"(r1), "=r"(r2), "=r"(r3) : "r"(a));
}
__device__ __forceinline__ void mma16816(float* c, const uint32_t* A, uint32_t b0, uint32_t b1) {
    asm volatile("mma.sync.aligned.m16n8k16.row.col.f32.bf16.bf16.f32 "
                 "{%0,%1,%2,%3}, {%4,%5,%6,%7}, {%8,%9}, {%0,%1,%2,%3};"
                 : "+f"(c[0]), "+f"(c[1]), "+f"(c[2]), "+f"(c[3])
                 : "r"(A[0]), "r"(A[1]), "r"(A[2]), "r"(A[3]), "r"(b0), "r"(b1));
}
#define CP16(dst, src) asm volatile("cp.async.cg.shared.global [%0], [%1], 16;" :: "r"(dst), "l"(src))
#define CPCOMMIT()     asm volatile("cp.async.commit_group;" ::: "memory")
#define CPWAIT0()      asm volatile("cp.async.wait_group 0;" ::: "memory")

// split fp32 -> bf16 hi + bf16 residual(lo)
__device__ __forceinline__ void split2(float x0, float x1, uint32_t& hi, uint32_t& lo) {
    __nv_bfloat16 b0 = __float2bfloat16(x0), b1 = __float2bfloat16(x1);
    hi = (uint32_t)__bfloat16_as_ushort(b0) | ((uint32_t)__bfloat16_as_ushort(b1) << 16);
    lo = pkbf(x0 - __bfloat162float(b0), x1 - __bfloat162float(b1));
}

// convert a raw fp32 [128x64] chunk in smem -> bf16 hi/lo padded tiles
__device__ __forceinline__ void convert_chunk(const char* smem, uint32_t rawOff,
                                              char* hiBuf, char* loBuf, int t) {
    const float4* rb = (const float4*)(smem + rawOff);
#pragma unroll
    for (int kk = 0; kk < 4; ++kk) {
        int i = t + kk * THREADS;
        int row = i >> 4, c4 = i & 15;
        float4 v = rb[i];
        uint2 H, L;
        split2(v.x, v.y, H.x, L.x);
        split2(v.z, v.w, H.y, L.y);
        *(uint2*)(hiBuf + row * STRB + c4 * 8) = H;
        *(uint2*)(loBuf + row * STRB + c4 * 8) = L;
    }
}

// issue a 32KB chunk prefetch (128x64 fp32)
__device__ __forceinline__ void prefetch_chunk(uint32_t dst, const float* src, int t) {
    const char* s = (const char*)src;
#pragma unroll
    for (int kk = 0; kk < 4; ++kk) {
        int i = t + kk * THREADS;
        CP16(dst + i * 16, s + (size_t)i * 16);
    }
    CPCOMMIT();
}

// S phase with resident Q frags: per khi ldsm feed 4 mma, per klo ldsm 2 mma
__device__ __forceinline__ void s_phase_res(uint32_t khi, uint32_t klo,
                                            const uint32_t QAh[4][4], const uint32_t QAl[4][4],
                                            float acc[8][4], int lane, int wc) {
#pragma unroll
    for (int j = 0; j < 8; ++j) {
        uint32_t rowoff = (wc * 64 + j * 8 + (lane & 7)) * STRB + ((lane >> 3) * 8) * 2;
#pragma unroll
        for (int sp = 0; sp < 4; sp += 2) {
            uint32_t off = rowoff + sp * 32;
            uint32_t h0, h1, h2, h3, l0, l1, l2, l3;
            ldsm4(khi + off, h0, h1, h2, h3);
            mma16816(acc[j], QAh[sp],     h0, h1);
            mma16816(acc[j], QAh[sp + 1], h2, h3);
            mma16816(acc[j], QAl[sp],     h0, h1);
            mma16816(acc[j], QAl[sp + 1], h2, h3);
            ldsm4(klo + off, l0, l1, l2, l3);
            mma16816(acc[j], QAh[sp],     l0, l1);
            mma16816(acc[j], QAh[sp + 1], l2, l3);
        }
    }
}

__global__ void detect_mask_kind_kernel(const unsigned* __restrict__ mw) {
    __shared__ int s_i32bad, s_f32bad;
    if (threadIdx.x == 0) { s_i32bad = 0; s_f32bad = 0; }
    __syncthreads();
    for (int i = threadIdx.x; i < 1024; i += blockDim.x) {
        unsigned w = mw[i];
        if (w > 1u)                      atomicOr(&s_i32bad, 1);
        if (w != 0u && w != 0x3F800000u) atomicOr(&s_f32bad, 1);
    }
    __syncthreads();
    if (threadIdx.x == 0) g_mask_wide = (!s_i32bad || !s_f32bad) ? 1 : 0;
}

__global__ void __launch_bounds__(THREADS, 1)
sdpa_mma_kernel(const float* __restrict__ Qg,
                const float* __restrict__ Kg,
                const float* __restrict__ Vg,
                const unsigned char* __restrict__ Mg,
                float* __restrict__ ctx_out,
                float* __restrict__ w_out)
{
    extern __shared__ char smem[];
    const uint32_t sb = smem_u32(smem);

    const int t    = threadIdx.x;
    const int lane = t & 31;
    const int w    = t >> 5;
    const int wr   = w & 7;        // warp-row: q rows wr*16..+15
    const int wc   = w >> 3;       // warp-col: k half (0/1)
    const int tq   = lane >> 2;    // 0..7
    const int tc   = lane & 3;     // 0..3

    const int bh = blockIdx.y;
    const int q0 = blockIdx.x * MQT;
    const size_t row0 = (size_t)bh * S_LEN + q0;
    const int wide = g_mask_wide;

    float*     red    = (float*)(smem + O_RED);
    float*     sinv   = (float*)(smem + O_INV);
    uint32_t*  mcache = (uint32_t*)(smem + O_MC);

    const float* Kbh = Kg + (size_t)bh * S_LEN * DKD;
    const float* Vbh = Vg + (size_t)bh * S_LEN * DKD;

    const size_t qrA = row0 + wr * 16 + tq;
    const size_t qrB = qrA + 8;
    const size_t mrowA = qrA * (size_t)S_LEN;
    const size_t mrowB = qrB * (size_t)S_LEN;

    const uint32_t rawK = sb + O_RAW;
    const uint32_t rawV = sb + O_RAW + 32768;

    // ---- prologue: prefetch K0, V0 raw; stage Q bf16 hi/lo (scaled by 0.125*log2e) ----
    prefetch_chunk(rawK, Kbh, t);
    prefetch_chunk(rawV, Vbh, t);
    {
        const float4* q4 = (const float4*)(Qg + row0 * DKD);
#pragma unroll
        for (int kk = 0; kk < 4; ++kk) {
            int i = t + kk * THREADS;
            int row = i >> 4, c4 = i & 15;
            float4 v = q4[i];
            v.x *= QSCALE; v.y *= QSCALE; v.z *= QSCALE; v.w *= QSCALE;
            uint2 H, L;
            split2(v.x, v.y, H.x, L.x);
            split2(v.z, v.w, H.y, L.y);
            *(uint2*)(smem + O_QHI + row * STRB + c4 * 8) = H;
            *(uint2*)(smem + O_QLO + row * STRB + c4 * 8) = L;
        }
    }
    __syncthreads();   // Q tiles visible

    // ---- Q A-frags resident for entire kernel (chunk-invariant) ----
    uint32_t QAh[4][4], QAl[4][4];
#pragma unroll
    for (int s = 0; s < 4; ++s) {
        uint32_t off = (wr * 16 + (lane & 15)) * STRB + (s * 16 + (lane >> 4) * 8) * 2;
        ldsm4(sb + O_QHI + off, QAh[s][0], QAh[s][1], QAh[s][2], QAh[s][3]);
        ldsm4(sb + O_QLO + off, QAl[s][0], QAl[s][1], QAl[s][2], QAl[s][3]);
    }

    float ctx[8][4] = {};
    float rs0 = 0.f, rs1 = 0.f;

    // ================== PASS 1: S + exp + rowsum + PV (no weight writes) ==================
    for (int ch = 0; ch < NCH; ++ch) {
        const int kb = ch * NKC;

        // raw K & V ready -> convert both (single barrier pair per chunk)
        CPWAIT0();
        __syncthreads();
        convert_chunk(smem, O_RAW,         smem + O_KHI, smem + O_KLO, t);
        convert_chunk(smem, O_RAW + 32768, smem + O_VHI, smem + O_VLO, t);
        __syncthreads();
        if (ch < NCH - 1) {
            prefetch_chunk(rawK, Kbh + (size_t)(kb + NKC) * DKD, t);
            prefetch_chunk(rawV, Vbh + (size_t)(kb + NKC) * DKD, t);
        }

        // mask bits (gather from gmem early for latency cover; cache for pass 2)
        uint32_t mk = 0;
#pragma unroll
        for (int j = 0; j < 8; ++j) {
            int col = kb + wc * 64 + j * 8 + 2 * tc;
            uint32_t b0, b1, b2, b3;
            if (wide) {
                uint2 a = *(const uint2*)((const unsigned*)Mg + mrowA + col);
                uint2 b = *(const uint2*)((const unsigned*)Mg + mrowB + col);
                b0 = a.x != 0u; b1 = a.y != 0u; b2 = b.x != 0u; b3 = b.y != 0u;
            } else {
                unsigned short a = *(const unsigned short*)(Mg + mrowA + col);
                unsigned short b = *(const unsigned short*)(Mg + mrowB + col);
                b0 = (a & 0xFF) != 0; b1 = (a >> 8) != 0;
                b2 = (b & 0xFF) != 0; b3 = (b >> 8) != 0;
            }
            mk |= (b0 << (4 * j)) | (b1 << (4 * j + 1)) | (b2 << (4 * j + 2)) | (b3 << (4 * j + 3));
        }
        mcache[ch * THREADS + t] = mk;

        // S phase
        float acc[8][4] = {};
        s_phase_res(sb + O_KHI, sb + O_KLO, QAh, QAl, acc, lane, wc);

        // mask + exp2 + rowsum
#pragma unroll
        for (int j = 0; j < 8; ++j) {
            float e0 = ((mk >> (4 * j)) & 1u)     ? 0.f : ex2f(acc[j][0]);
            float e1 = ((mk >> (4 * j + 1)) & 1u) ? 0.f : ex2f(acc[j][1]);
            float e2 = ((mk >> (4 * j + 2)) & 1u) ? 0.f : ex2f(acc[j][2]);
            float e3 = ((mk >> (4 * j + 3)) & 1u) ? 0.f : ex2f(acc[j][3]);
            rs0 += e0 + e1;  rs1 += e2 + e3;
            acc[j][0] = e0; acc[j][1] = e1; acc[j][2] = e2; acc[j][3] = e3;
        }

        // repack P as bf16 hi/lo A-frags
        uint32_t PAh[4][4], PAl[4][4];
#pragma unroll
        for (int s = 0; s < 4; ++s) {
            split2(acc[2 * s][0],     acc[2 * s][1],     PAh[s][0], PAl[s][0]);
            split2(acc[2 * s][2],     acc[2 * s][3],     PAh[s][1], PAl[s][1]);
            split2(acc[2 * s + 1][0], acc[2 * s + 1][1], PAh[s][2], PAl[s][2]);
            split2(acc[2 * s + 1][2], acc[2 * s + 1][3], PAh[s][3], PAl[s][3]);
        }

        // PV phase
#pragma unroll
        for (int s = 0; s < 4; ++s) {
#pragma unroll
            for (int j2 = 0; j2 < 4; ++j2) {
                uint32_t vrow = (wc * 64 + s * 16 + (lane & 15));
                uint32_t vcol = (j2 * 16 + (lane >> 4) * 8) * 2;
                uint32_t bh0, bh1, bh2, bh3, bl0, bl1, bl2, bl3;
                ldsm4t(sb + O_VHI + vrow * STRB + vcol, bh0, bh1, bh2, bh3);
                ldsm4t(sb + O_VLO + vrow * STRB + vcol, bl0, bl1, bl2, bl3);
                mma16816(ctx[2 * j2],     PAh[s], bh0, bh1);
                mma16816(ctx[2 * j2],     PAl[s], bh0, bh1);
                mma16816(ctx[2 * j2],     PAh[s], bl0, bl1);
                mma16816(ctx[2 * j2 + 1], PAh[s], bh2, bh3);
                mma16816(ctx[2 * j2 + 1], PAl[s], bh2, bh3);
                mma16816(ctx[2 * j2 + 1], PAh[s], bl2, bl3);
            }
        }
    }

    // ---- pass-2 prefetch: K0 (raw buffers free) ----
    prefetch_chunk(rawK, Kbh, t);

    // ================= row-sum reduction =================
    __syncthreads();
    if (t < 128) red[t] = 0.f;
    __syncthreads();
    rs0 += __shfl_xor_sync(0xffffffffu, rs0, 1);
    rs0 += __shfl_xor_sync(0xffffffffu, rs0, 2);
    rs1 += __shfl_xor_sync(0xffffffffu, rs1, 1);
    rs1 += __shfl_xor_sync(0xffffffffu, rs1, 2);
    if (tc == 0) {
        atomicAdd(&red[wr * 16 + tq], rs0);
        atomicAdd(&red[wr * 16 + tq + 8], rs1);
    }
    // ctx partials into the (now dead) bf16 K/V tile region
    {
        float* cbuf = (float*)(smem + O_KHI) + wc * 8192;
#pragma unroll
        for (int j = 0; j < 8; ++j) {
            int row = wr * 16 + tq, col = j * 8 + 2 * tc;
            *(float2*)(cbuf + row * 64 + col)       = make_float2(ctx[j][0], ctx[j][1]);
            *(float2*)(cbuf + (row + 8) * 64 + col) = make_float2(ctx[j][2], ctx[j][3]);
        }
    }
    __syncthreads();
    if (t < 128) sinv[t] = 1.0f / red[t];
    __syncthreads();

    // ================= ctx combine + write =================
    {
        const float4* b0 = (const float4*)(smem + O_KHI);
        const float4* b1 = (const float4*)(smem + O_KHI) + 2048;
#pragma unroll
        for (int kk = 0; kk < 4; ++kk) {
            int i = t + kk * THREADS;
            int row = i >> 4, c4 = i & 15;
            float4 a = b0[i], b = b1[i];
            float iv = sinv[row];
            float4 o;
            o.x = (a.x + b.x) * iv; o.y = (a.y + b.y) * iv;
            o.z = (a.z + b.z) * iv; o.w = (a.w + b.w) * iv;
            *(float4*)(ctx_out + (row0 + row) * DKD + c4 * 4) = o;
        }
    }

    // ================== PASS 2: recompute S, write normalized weights ==================
    const float ivA = sinv[wr * 16 + tq];
    const float ivB = sinv[wr * 16 + tq + 8];
    for (int ch = 0; ch < NCH; ++ch) {
        const int kb = ch * NKC;
        CPWAIT0();
        __syncthreads();   // also guards prior-iteration KHI/KLO readers
        convert_chunk(smem, O_RAW, smem + O_KHI, smem + O_KLO, t);
        __syncthreads();
        if (ch < NCH - 1) prefetch_chunk(rawK, Kbh + (size_t)(kb + NKC) * DKD, t);

        float acc[8][4] = {};
        s_phase_res(sb + O_KHI, sb + O_KLO, QAh, QAl, acc, lane, wc);

        const uint32_t mk = mcache[ch * THREADS + t];
#pragma unroll
        for (int j = 0; j < 8; ++j) {
            float e0 = ((mk >> (4 * j)) & 1u)     ? 0.f : ex2f(acc[j][0]) * ivA;
            float e1 = ((mk >> (4 * j + 1)) & 1u) ? 0.f : ex2f(acc[j][1]) * ivA;
            float e2 = ((mk >> (4 * j + 2)) & 1u) ? 0.f : ex2f(acc[j][2]) * ivB;
            float e3 = ((mk >> (4 * j + 3)) & 1u) ? 0.f : ex2f(acc[j][3]) * ivB;
            int col = kb + wc * 64 + j * 8 + 2 * tc;
            __stcs((float2*)(w_out + mrowA + col), make_float2(e0, e1));
            __stcs((float2*)(w_out + mrowB + col), make_float2(e2, e3));
        }
    }
}

extern "C" void kernel_launch(void* const* d_in, const int* in_sizes, int n_in,
                              void* d_out, int out_size)
{
    const float*         Q = (const float*)d_in[0];
    const float*         K = (const float*)d_in[1];
    const float*         V = (const float*)d_in[2];
    const unsigned char* M = (const unsigned char*)d_in[3];

    float* ctx = (float*)d_out;
    float* wts = (float*)d_out + (size_t)BHN * S_LEN * DKD;

    cudaFuncSetAttribute(sdpa_mma_kernel,
                         cudaFuncAttributeMaxDynamicSharedMemorySize, SMEMB);

    detect_mask_kind_kernel<<<1, 256>>>((const unsigned*)M);

    dim3 grid(S_LEN / MQT, BHN);   // (16, 32) = 512 CTAs
    sdpa_mma_kernel<<<grid, THREADS, SMEMB>>>(Q, K, V, M, ctx, wts);
}

// round 8
// speedup vs baseline: 6.5800x; 1.1115x over previous
#include <cuda_runtime.h>
#include <cuda_bf16.h>
#include <cstdint>
#include <cstddef>

#define S_LEN   2048
#define DKD     64
#define BHN     32
#define MQT     128          // q rows per CTA
#define NKC     128          // k cols per chunk
#define NCH     (S_LEN / NKC)
#define THREADS 512

// 0.125 * log2(e): fold softmax scale + exp->exp2 conversion into Q
#define QSCALE 0.1803368801111831f

#define TILE_B  16384        // one 128x64 bf16 tile, SW128 swizzled, 128B rows
#define CHUNK_B 65536        // Khi,Klo,Vhi,Vlo per chunk

// ---- smem byte offsets ----
#define O_BUF0 0
#define O_BUF1 65536
#define O_MC   131072        // mask cache 32KB (doubles as Q staging at startup)
#define O_RED  163840
#define O_INV  164352
#define SMEMB  164864

#define SWZ(o) ((o) ^ (((o) >> 3) & 0x70))

// bf16 hi/lo K,V tiles, pre-swizzled ldmatrix-ready images (32 MB scratch)
__device__ __align__(16) unsigned char g_kv16[(size_t)BHN * NCH * CHUNK_B];
__device__ int g_mask_wide;

// ---------------- helpers ----------------
__device__ __forceinline__ uint32_t smem_u32(const void* p) {
    uint32_t a;
    asm("{ .reg .u64 t; cvta.to.shared.u64 t, %1; cvt.u32.u64 %0, t; }" : "=r"(a) : "l"(p));
    return a;
}
__device__ __forceinline__ float ex2f(float x) {
    float y; asm("ex2.approx.f32 %0, %1;" : "=f"(y) : "f"(x)); return y;
}
__device__ __forceinline__ uint32_t pkbf(float lo, float hi) {  // lo -> bits[15:0]
    uint32_t r; asm("cvt.rn.bf16x2.f32 %0, %1, %2;" : "=r"(r) : "f"(hi), "f"(lo)); return r;
}
__device__ __forceinline__ void ldsm4(uint32_t a, uint32_t& r0, uint32_t& r1, uint32_t& r2, uint32_t& r3) {
    asm volatile("ldmatrix.sync.aligned.m8n8.x4.shared.b16 {%0,%1,%2,%3}, [%4];"
                 : "=r"(r0), "=r"(r1), "=r"(r2), "=r"(r3) : "r"(a));
}
__device__ __forceinline__ void ldsm4t(uint32_t a, uint32_t& r0, uint32_t& r1, uint32_t& r2, uint32_t& r3) {
    asm volatile("ldmatrix.sync.aligned.m8n8.x4.trans.shared.b16 {%0,%1,%2,%3}, [%4];"
                 : "=r"(r0), "=r"(r1), "=r"(r2), "=r"(r3) : "r"(a));
}
__device__ __forceinline__ void mma16816(float* c, const uint32_t* A, uint32_t b0, uint32_t b1) {
    asm volatile("mma.sync.aligned.m16n8k16.row.col.f32.bf16.bf16.f32 "
                 "{%0,%1,%2,%3}, {%4,%5,%6,%7}, {%8,%9}, {%0,%1,%2,%3};"
                 : "+f"(c[0]), "+f"(c[1]), "+f"(c[2]), "+f"(c[3])
                 : "r"(A[0]), "r"(A[1]), "r"(A[2]), "r"(A[3]), "r"(b0), "r"(b1));
}
#define CP16(dst, src) asm volatile("cp.async.cg.shared.global [%0], [%1], 16;" :: "r"(dst), "l"(src))
#define CPCOMMIT()     asm volatile("cp.async.commit_group;" ::: "memory")
#define CPWAIT0()      asm volatile("cp.async.wait_group 0;" ::: "memory")

// split fp32 -> bf16 hi + bf16 residual(lo)
__device__ __forceinline__ void split2(float x0, float x1, uint32_t& hi, uint32_t& lo) {
    __nv_bfloat16 b0 = __float2bfloat16(x0), b1 = __float2bfloat16(x1);
    hi = (uint32_t)__bfloat16_as_ushort(b0) | ((uint32_t)__bfloat16_as_ushort(b1) << 16);
    lo = pkbf(x0 - __bfloat162float(b0), x1 - __bfloat162float(b1));
}

// ---------------- preprocessing: K/V fp32 -> swizzled bf16 hi/lo tiles ----------------
__global__ void preconvert_kernel(const float* __restrict__ K, const float* __restrict__ V) {
    const int ch = blockIdx.x, bh = blockIdx.y, t = threadIdx.x;   // 256 threads
    const float* ks = K + ((size_t)bh * S_LEN + ch * NKC) * DKD;
    const float* vs = V + ((size_t)bh * S_LEN + ch * NKC) * DKD;
    unsigned char* dst = g_kv16 + ((size_t)bh * NCH + ch) * CHUNK_B;
#pragma unroll
    for (int it = 0; it < 4; ++it) {
        int i = t + it * 256;           // 8-float group 0..1023
        int row = i >> 3, c8 = i & 7;
        uint32_t o = SWZ((uint32_t)(row * 128 + c8 * 16));
        float4 a = *(const float4*)(ks + row * DKD + c8 * 8);
        float4 b = *(const float4*)(ks + row * DKD + c8 * 8 + 4);
        uint4 H, L;
        split2(a.x, a.y, H.x, L.x); split2(a.z, a.w, H.y, L.y);
        split2(b.x, b.y, H.z, L.z); split2(b.z, b.w, H.w, L.w);
        *(uint4*)(dst + o)          = H;
        *(uint4*)(dst + TILE_B + o) = L;
        a = *(const float4*)(vs + row * DKD + c8 * 8);
        b = *(const float4*)(vs + row * DKD + c8 * 8 + 4);
        split2(a.x, a.y, H.x, L.x); split2(a.z, a.w, H.y, L.y);
        split2(b.x, b.y, H.z, L.z); split2(b.z, b.w, H.w, L.w);
        *(uint4*)(dst + 2 * TILE_B + o) = H;
        *(uint4*)(dst + 3 * TILE_B + o) = L;
    }
}

__global__ void detect_mask_kind_kernel(const unsigned* __restrict__ mw) {
    __shared__ int s_i32bad, s_f32bad;
    if (threadIdx.x == 0) { s_i32bad = 0; s_f32bad = 0; }
    __syncthreads();
    for (int i = threadIdx.x; i < 1024; i += blockDim.x) {
        unsigned w = mw[i];
        if (w > 1u)                      atomicOr(&s_i32bad, 1);
        if (w != 0u && w != 0x3F800000u) atomicOr(&s_f32bad, 1);
    }
    __syncthreads();
    if (threadIdx.x == 0) g_mask_wide = (!s_i32bad || !s_f32bad) ? 1 : 0;
}

// copy nbytes (multiple of 16*THREADS) from scratch gmem -> smem buffer
__device__ __forceinline__ void dma_tiles(uint32_t dst, const unsigned char* src, int t, int n16) {
#pragma unroll
    for (int kk = 0; kk < 8; ++kk) {
        if (kk * THREADS >= n16) break;
        int i = t + kk * THREADS;
        CP16(dst + i * 16, src + (size_t)i * 16);
    }
    CPCOMMIT();
}

// S phase on swizzled tiles with resident Q frags
__device__ __forceinline__ void s_phase_res(uint32_t khi, uint32_t klo,
                                            const uint32_t QAh[4][4], const uint32_t QAl[4][4],
                                            float acc[8][4], int lane, int wc) {
#pragma unroll
    for (int j = 0; j < 8; ++j) {
        uint32_t base = (uint32_t)((wc * 64 + j * 8 + (lane & 7)) * 128 + (lane >> 3) * 16);
        uint32_t o0 = SWZ(base), o1 = SWZ(base + 64);
        uint32_t h0, h1, h2, h3, l0, l1, l2, l3;
        ldsm4(khi + o0, h0, h1, h2, h3);
        mma16816(acc[j], QAh[0], h0, h1);
        mma16816(acc[j], QAh[1], h2, h3);
        mma16816(acc[j], QAl[0], h0, h1);
        mma16816(acc[j], QAl[1], h2, h3);
        ldsm4(klo + o0, l0, l1, l2, l3);
        mma16816(acc[j], QAh[0], l0, l1);
        mma16816(acc[j], QAh[1], l2, l3);
        ldsm4(khi + o1, h0, h1, h2, h3);
        mma16816(acc[j], QAh[2], h0, h1);
        mma16816(acc[j], QAh[3], h2, h3);
        mma16816(acc[j], QAl[2], h0, h1);
        mma16816(acc[j], QAl[3], h2, h3);
        ldsm4(klo + o1, l0, l1, l2, l3);
        mma16816(acc[j], QAh[2], l0, l1);
        mma16816(acc[j], QAh[3], l2, l3);
    }
}

__global__ void __launch_bounds__(THREADS, 1)
sdpa_mma_kernel(const float* __restrict__ Qg,
                const unsigned char* __restrict__ Mg,
                float* __restrict__ ctx_out,
                float* __restrict__ w_out)
{
    extern __shared__ char smem[];
    const uint32_t sb = smem_u32(smem);

    const int t    = threadIdx.x;
    const int lane = t & 31;
    const int w    = t >> 5;
    const int wr   = w & 7;        // warp-row: q rows wr*16..+15
    const int wc   = w >> 3;       // warp-col: k half (0/1)
    const int tq   = lane >> 2;    // 0..7
    const int tc   = lane & 3;     // 0..3

    const int bh = blockIdx.y;
    const int q0 = blockIdx.x * MQT;
    const size_t row0 = (size_t)bh * S_LEN + q0;
    const int wide = g_mask_wide;

    float*     red    = (float*)(smem + O_RED);
    float*     sinv   = (float*)(smem + O_INV);
    uint32_t*  mcache = (uint32_t*)(smem + O_MC);

    const unsigned char* kvsrc = g_kv16 + (size_t)bh * NCH * CHUNK_B;

    const size_t qrA = row0 + wr * 16 + tq;
    const size_t qrB = qrA + 8;
    const size_t mrowA = qrA * (size_t)S_LEN;
    const size_t mrowB = qrB * (size_t)S_LEN;

    // ---- stage Q (scaled) into swizzled tiles in the mcache region ----
    {
        const float* qs = Qg + row0 * DKD;
#pragma unroll
        for (int it = 0; it < 2; ++it) {
            int i = t + it * THREADS;      // group 0..1023
            int row = i >> 3, c8 = i & 7;
            uint32_t o = SWZ((uint32_t)(row * 128 + c8 * 16));
            float4 a = *(const float4*)(qs + row * DKD + c8 * 8);
            float4 b = *(const float4*)(qs + row * DKD + c8 * 8 + 4);
            a.x *= QSCALE; a.y *= QSCALE; a.z *= QSCALE; a.w *= QSCALE;
            b.x *= QSCALE; b.y *= QSCALE; b.z *= QSCALE; b.w *= QSCALE;
            uint4 H, L;
            split2(a.x, a.y, H.x, L.x); split2(a.z, a.w, H.y, L.y);
            split2(b.x, b.y, H.z, L.z); split2(b.z, b.w, H.w, L.w);
            *(uint4*)(smem + O_MC + o)          = H;
            *(uint4*)(smem + O_MC + TILE_B + o) = L;
        }
    }
    __syncthreads();

    // ---- Q A-frags resident for entire kernel ----
    uint32_t QAh[4][4], QAl[4][4];
#pragma unroll
    for (int s = 0; s < 4; ++s) {
        uint32_t off = SWZ((uint32_t)((wr * 16 + (lane & 15)) * 128 + s * 32 + (lane >> 4) * 16));
        ldsm4(sb + O_MC + off,          QAh[s][0], QAh[s][1], QAh[s][2], QAh[s][3]);
        ldsm4(sb + O_MC + TILE_B + off, QAl[s][0], QAl[s][1], QAl[s][2], QAl[s][3]);
    }
    __syncthreads();   // frags loaded; mcache region reusable

    // ---- prologue prefetch chunk0 -> buf0 ----
    dma_tiles(sb + O_BUF0, kvsrc, t, 4096);

    float ctx[8][4] = {};
    float rs0 = 0.f, rs1 = 0.f;

    // ================== PASS 1: S + exp + rowsum + PV ==================
    for (int ch = 0; ch < NCH; ++ch) {
        const int kb = ch * NKC;
        const uint32_t buf = sb + ((ch & 1) ? O_BUF1 : O_BUF0);

        CPWAIT0();
        __syncthreads();   // chunk ch ready; prev compute done everywhere
        if (ch + 1 < NCH)
            dma_tiles(sb + ((ch & 1) ? O_BUF0 : O_BUF1),
                      kvsrc + (size_t)(ch + 1) * CHUNK_B, t, 4096);

        // mask bits (gather early; cache for pass 2)
        uint32_t mk = 0;
#pragma unroll
        for (int j = 0; j < 8; ++j) {
            int col = kb + wc * 64 + j * 8 + 2 * tc;
            uint32_t b0, b1, b2, b3;
            if (wide) {
                uint2 a = *(const uint2*)((const unsigned*)Mg + mrowA + col);
                uint2 b = *(const uint2*)((const unsigned*)Mg + mrowB + col);
                b0 = a.x != 0u; b1 = a.y != 0u; b2 = b.x != 0u; b3 = b.y != 0u;
            } else {
                unsigned short a = *(const unsigned short*)(Mg + mrowA + col);
                unsigned short b = *(const unsigned short*)(Mg + mrowB + col);
                b0 = (a & 0xFF) != 0; b1 = (a >> 8) != 0;
                b2 = (b & 0xFF) != 0; b3 = (b >> 8) != 0;
            }
            mk |= (b0 << (4 * j)) | (b1 << (4 * j + 1)) | (b2 << (4 * j + 2)) | (b3 << (4 * j + 3));
        }
        mcache[ch * THREADS + t] = mk;

        // S phase
        float acc[8][4] = {};
        s_phase_res(buf, buf + TILE_B, QAh, QAl, acc, lane, wc);

        // mask + exp2 + rowsum
#pragma unroll
        for (int j = 0; j < 8; ++j) {
            float e0 = ((mk >> (4 * j)) & 1u)     ? 0.f : ex2f(acc[j][0]);
            float e1 = ((mk >> (4 * j + 1)) & 1u) ? 0.f : ex2f(acc[j][1]);
            float e2 = ((mk >> (4 * j + 2)) & 1u) ? 0.f : ex2f(acc[j][2]);
            float e3 = ((mk >> (4 * j + 3)) & 1u) ? 0.f : ex2f(acc[j][3]);
            rs0 += e0 + e1;  rs1 += e2 + e3;
            acc[j][0] = e0; acc[j][1] = e1; acc[j][2] = e2; acc[j][3] = e3;
        }

        // repack P as bf16 hi/lo A-frags
        uint32_t PAh[4][4], PAl[4][4];
#pragma unroll
        for (int s = 0; s < 4; ++s) {
            split2(acc[2 * s][0],     acc[2 * s][1],     PAh[s][0], PAl[s][0]);
            split2(acc[2 * s][2],     acc[2 * s][3],     PAh[s][1], PAl[s][1]);
            split2(acc[2 * s + 1][0], acc[2 * s + 1][1], PAh[s][2], PAl[s][2]);
            split2(acc[2 * s + 1][2], acc[2 * s + 1][3], PAh[s][3], PAl[s][3]);
        }

        // PV phase
        const uint32_t vhi = buf + 2 * TILE_B, vlo = buf + 3 * TILE_B;
#pragma unroll
        for (int s = 0; s < 4; ++s) {
#pragma unroll
            for (int j2 = 0; j2 < 4; ++j2) {
                uint32_t o = SWZ((uint32_t)((wc * 64 + s * 16 + (lane & 15)) * 128
                                            + j2 * 32 + (lane >> 4) * 16));
                uint32_t bh0, bh1, bh2, bh3, bl0, bl1, bl2, bl3;
                ldsm4t(vhi + o, bh0, bh1, bh2, bh3);
                ldsm4t(vlo + o, bl0, bl1, bl2, bl3);
                mma16816(ctx[2 * j2],     PAh[s], bh0, bh1);
                mma16816(ctx[2 * j2],     PAl[s], bh0, bh1);
                mma16816(ctx[2 * j2],     PAh[s], bl0, bl1);
                mma16816(ctx[2 * j2 + 1], PAh[s], bh2, bh3);
                mma16816(ctx[2 * j2 + 1], PAl[s], bh2, bh3);
                mma16816(ctx[2 * j2 + 1], PAh[s], bl2, bl3);
            }
        }
    }

    __syncthreads();   // everyone done with buffers
    // pass-2 prefetch: K tiles of chunk0 -> buf0 (32 KB)
    dma_tiles(sb + O_BUF0, kvsrc, t, 2048);

    // ================= row-sum reduction =================
    if (t < 128) red[t] = 0.f;
    __syncthreads();
    rs0 += __shfl_xor_sync(0xffffffffu, rs0, 1);
    rs0 += __shfl_xor_sync(0xffffffffu, rs0, 2);
    rs1 += __shfl_xor_sync(0xffffffffu, rs1, 1);
    rs1 += __shfl_xor_sync(0xffffffffu, rs1, 2);
    if (tc == 0) {
        atomicAdd(&red[wr * 16 + tq], rs0);
        atomicAdd(&red[wr * 16 + tq + 8], rs1);
    }
    // ctx partials into buf1 region (dead until pass-2 chunk1)
    {
        float* cbuf = (float*)(smem + O_BUF1) + wc * 8192;
#pragma unroll
        for (int j = 0; j < 8; ++j) {
            int row = wr * 16 + tq, col = j * 8 + 2 * tc;
            *(float2*)(cbuf + row * 64 + col)       = make_float2(ctx[j][0], ctx[j][1]);
            *(float2*)(cbuf + (row + 8) * 64 + col) = make_float2(ctx[j][2], ctx[j][3]);
        }
    }
    __syncthreads();
    if (t < 128) sinv[t] = 1.0f / red[t];
    __syncthreads();

    // ================= ctx combine + write =================
    {
        const float4* b0 = (const float4*)(smem + O_BUF1);
        const float4* b1 = (const float4*)(smem + O_BUF1) + 2048;
#pragma unroll
        for (int kk = 0; kk < 4; ++kk) {
            int i = t + kk * THREADS;
            int row = i >> 4, c4 = i & 15;
            float4 a = b0[i], b = b1[i];
            float iv = sinv[row];
            float4 o;
            o.x = (a.x + b.x) * iv; o.y = (a.y + b.y) * iv;
            o.z = (a.z + b.z) * iv; o.w = (a.w + b.w) * iv;
            *(float4*)(ctx_out + (row0 + row) * DKD + c4 * 4) = o;
        }
    }
    __syncthreads();   // buf1 free again

    // ================== PASS 2: recompute S, write normalized weights ==================
    const float ivA = sinv[wr * 16 + tq];
    const float ivB = sinv[wr * 16 + tq + 8];
    for (int ch = 0; ch < NCH; ++ch) {
        const int kb = ch * NKC;
        const uint32_t buf = sb + ((ch & 1) ? O_BUF1 : O_BUF0);

        CPWAIT0();
        __syncthreads();
        if (ch + 1 < NCH)
            dma_tiles(sb + ((ch & 1) ? O_BUF0 : O_BUF1),
                      kvsrc + (size_t)(ch + 1) * CHUNK_B, t, 2048);

        float acc[8][4] = {};
        s_phase_res(buf, buf + TILE_B, QAh, QAl, acc, lane, wc);

        const uint32_t mk = mcache[ch * THREADS + t];
#pragma unroll
        for (int j = 0; j < 8; ++j) {
            float e0 = ((mk >> (4 * j)) & 1u)     ? 0.f : ex2f(acc[j][0]) * ivA;
            float e1 = ((mk >> (4 * j + 1)) & 1u) ? 0.f : ex2f(acc[j][1]) * ivA;
            float e2 = ((mk >> (4 * j + 2)) & 1u) ? 0.f : ex2f(acc[j][2]) * ivB;
            float e3 = ((mk >> (4 * j + 3)) & 1u) ? 0.f : ex2f(acc[j][3]) * ivB;
            int col = kb + wc * 64 + j * 8 + 2 * tc;
            __stcs((float2*)(w_out + mrowA + col), make_float2(e0, e1));
            __stcs((float2*)(w_out + mrowB + col), make_float2(e2, e3));
        }
    }
}

extern "C" void kernel_launch(void* const* d_in, const int* in_sizes, int n_in,
                              void* d_out, int out_size)
{
    const float*         Q = (const float*)d_in[0];
    const float*         K = (const float*)d_in[1];
    const float*         V = (const float*)d_in[2];
    const unsigned char* M = (const unsigned char*)d_in[3];

    float* ctx = (float*)d_out;
    float* wts = (float*)d_out + (size_t)BHN * S_LEN * DKD;

    cudaFuncSetAttribute(sdpa_mma_kernel,
                         cudaFuncAttributeMaxDynamicSharedMemorySize, SMEMB);

    detect_mask_kind_kernel<<<1, 256>>>((const unsigned*)M);
    preconvert_kernel<<<dim3(NCH, BHN), 256>>>(K, V);

    dim3 grid(S_LEN / MQT, BHN);   // (16, 32) = 512 CTAs
    sdpa_mma_kernel<<<grid, THREADS, SMEMB>>>(Q, M, ctx, wts);
}

// round 9
// speedup vs baseline: 7.3635x; 1.1191x over previous
#include <cuda_runtime.h>
#include <cuda_bf16.h>
#include <cstdint>
#include <cstddef>

#define S_LEN   2048
#define DKD     64
#define BHN     32
#define MQT     64           // q rows per CTA
#define NKC     128          // k cols per chunk
#define NCH     (S_LEN / NKC)
#define THREADS 512

// 0.125 * log2(e): fold softmax scale + exp->exp2 conversion into Q
#define QSCALE 0.1803368801111831f

#define TILE_B  16384        // one 128x64 bf16 K/V tile, SW128 swizzled, 128B rows
#define CHUNK_B 65536        // Khi,Klo,Vhi,Vlo per chunk
#define QTILE_B 8192         // 64x64 bf16 Q tile

// ---- smem byte offsets ----
#define O_BUF0 0
#define O_BUF1 65536
#define O_MC   131072        // mask cache 32KB (doubles as Q staging at startup)
#define O_RED  163840        // 64 floats
#define O_INV  164096        // 64 floats
#define SMEMB  164352

#define SWZ(o) ((o) ^ (((o) >> 3) & 0x70))

// bf16 hi/lo K,V tiles, pre-swizzled ldmatrix-ready images (32 MB scratch)
__device__ __align__(16) unsigned char g_kv16[(size_t)BHN * NCH * CHUNK_B];
__device__ int g_mask_wide;

// ---------------- helpers ----------------
__device__ __forceinline__ uint32_t smem_u32(const void* p) {
    uint32_t a;
    asm("{ .reg .u64 t; cvta.to.shared.u64 t, %1; cvt.u32.u64 %0, t; }" : "=r"(a) : "l"(p));
    return a;
}
__device__ __forceinline__ float ex2f(float x) {
    float y; asm("ex2.approx.f32 %0, %1;" : "=f"(y) : "f"(x)); return y;
}
__device__ __forceinline__ uint32_t pkbf(float lo, float hi) {  // lo -> bits[15:0]
    uint32_t r; asm("cvt.rn.bf16x2.f32 %0, %1, %2;" : "=r"(r) : "f"(hi), "f"(lo)); return r;
}
__device__ __forceinline__ void ldsm4(uint32_t a, uint32_t& r0, uint32_t& r1, uint32_t& r2, uint32_t& r3) {
    asm volatile("ldmatrix.sync.aligned.m8n8.x4.shared.b16 {%0,%1,%2,%3}, [%4];"
                 : "=r"(r0), "=r"(r1), "=r"(r2), "=r"(r3) : "r"(a));
}
__device__ __forceinline__ void ldsm4t(uint32_t a, uint32_t& r0, uint32_t& r1, uint32_t& r2, uint32_t& r3) {
    asm volatile("ldmatrix.sync.aligned.m8n8.x4.trans.shared.b16 {%0,%1,%2,%3}, [%4];"
                 : "=r"(r0), "=r"(r1), "=r"(r2), "=r"(r3) : "r"(a));
}
__device__ __forceinline__ void mma16816(float* c, const uint32_t* A, uint32_t b0, uint32_t b1) {
    asm volatile("mma.sync.aligned.m16n8k16.row.col.f32.bf16.bf16.f32 "
                 "{%0,%1,%2,%3}, {%4,%5,%6,%7}, {%8,%9}, {%0,%1,%2,%3};"
                 : "+f"(c[0]), "+f"(c[1]), "+f"(c[2]), "+f"(c[3])
                 : "r"(A[0]), "r"(A[1]), "r"(A[2]), "r"(A[3]), "r"(b0), "r"(b1));
}
#define CP16(dst, src) asm volatile("cp.async.cg.shared.global [%0], [%1], 16;" :: "r"(dst), "l"(src))
#define CPCOMMIT()     asm volatile("cp.async.commit_group;" ::: "memory")
#define CPWAIT0()      asm volatile("cp.async.wait_group 0;" ::: "memory")

// split fp32 -> bf16 hi + bf16 residual(lo)
__device__ __forceinline__ void split2(float x0, float x1, uint32_t& hi, uint32_t& lo) {
    __nv_bfloat16 b0 = __float2bfloat16(x0), b1 = __float2bfloat16(x1);
    hi = (uint32_t)__bfloat16_as_ushort(b0) | ((uint32_t)__bfloat16_as_ushort(b1) << 16);
    lo = pkbf(x0 - __bfloat162float(b0), x1 - __bfloat162float(b1));
}

// ---------------- preprocessing: K/V fp32 -> swizzled bf16 hi/lo tiles ----------------
__global__ void preconvert_kernel(const float* __restrict__ K, const float* __restrict__ V) {
    const int ch = blockIdx.x, bh = blockIdx.y, t = threadIdx.x;   // 256 threads
    const float* ks = K + ((size_t)bh * S_LEN + ch * NKC) * DKD;
    const float* vs = V + ((size_t)bh * S_LEN + ch * NKC) * DKD;
    unsigned char* dst = g_kv16 + ((size_t)bh * NCH + ch) * CHUNK_B;
#pragma unroll
    for (int it = 0; it < 4; ++it) {
        int i = t + it * 256;           // 8-float group 0..1023
        int row = i >> 3, c8 = i & 7;
        uint32_t o = SWZ((uint32_t)(row * 128 + c8 * 16));
        float4 a = *(const float4*)(ks + row * DKD + c8 * 8);
        float4 b = *(const float4*)(ks + row * DKD + c8 * 8 + 4);
        uint4 H, L;
        split2(a.x, a.y, H.x, L.x); split2(a.z, a.w, H.y, L.y);
        split2(b.x, b.y, H.z, L.z); split2(b.z, b.w, H.w, L.w);
        *(uint4*)(dst + o)          = H;
        *(uint4*)(dst + TILE_B + o) = L;
        a = *(const float4*)(vs + row * DKD + c8 * 8);
        b = *(const float4*)(vs + row * DKD + c8 * 8 + 4);
        split2(a.x, a.y, H.x, L.x); split2(a.z, a.w, H.y, L.y);
        split2(b.x, b.y, H.z, L.z); split2(b.z, b.w, H.w, L.w);
        *(uint4*)(dst + 2 * TILE_B + o) = H;
        *(uint4*)(dst + 3 * TILE_B + o) = L;
    }
}

__global__ void detect_mask_kind_kernel(const unsigned* __restrict__ mw) {
    __shared__ int s_i32bad, s_f32bad;
    if (threadIdx.x == 0) { s_i32bad = 0; s_f32bad = 0; }
    __syncthreads();
    for (int i = threadIdx.x; i < 1024; i += blockDim.x) {
        unsigned w = mw[i];
        if (w > 1u)                      atomicOr(&s_i32bad, 1);
        if (w != 0u && w != 0x3F800000u) atomicOr(&s_f32bad, 1);
    }
    __syncthreads();
    if (threadIdx.x == 0) g_mask_wide = (!s_i32bad || !s_f32bad) ? 1 : 0;
}

// copy 16*n16 bytes from scratch gmem -> smem buffer
__device__ __forceinline__ void dma_tiles(uint32_t dst, const unsigned char* src, int t, int n16) {
#pragma unroll
    for (int kk = 0; kk < 8; ++kk) {
        if (kk * THREADS >= n16) break;
        int i = t + kk * THREADS;
        CP16(dst + i * 16, src + (size_t)i * 16);
    }
    CPCOMMIT();
}

// S phase (warp covers 16 q x 32 k): 4 j-frags, 12 mma each
__device__ __forceinline__ void s_phase_res(uint32_t khi, uint32_t klo,
                                            const uint32_t QAh[4][4], const uint32_t QAl[4][4],
                                            float acc[4][4], int lane, int wc) {
#pragma unroll
    for (int j = 0; j < 4; ++j) {
        uint32_t base = (uint32_t)((wc * 32 + j * 8 + (lane & 7)) * 128 + (lane >> 3) * 16);
        uint32_t o0 = SWZ(base), o1 = SWZ(base + 64);
        uint32_t h0, h1, h2, h3, l0, l1, l2, l3;
        ldsm4(khi + o0, h0, h1, h2, h3);
        mma16816(acc[j], QAh[0], h0, h1);
        mma16816(acc[j], QAh[1], h2, h3);
        mma16816(acc[j], QAl[0], h0, h1);
        mma16816(acc[j], QAl[1], h2, h3);
        ldsm4(klo + o0, l0, l1, l2, l3);
        mma16816(acc[j], QAh[0], l0, l1);
        mma16816(acc[j], QAh[1], l2, l3);
        ldsm4(khi + o1, h0, h1, h2, h3);
        mma16816(acc[j], QAh[2], h0, h1);
        mma16816(acc[j], QAh[3], h2, h3);
        mma16816(acc[j], QAl[2], h0, h1);
        mma16816(acc[j], QAl[3], h2, h3);
        ldsm4(klo + o1, l0, l1, l2, l3);
        mma16816(acc[j], QAh[2], l0, l1);
        mma16816(acc[j], QAh[3], l2, l3);
    }
}

__global__ void __launch_bounds__(THREADS, 1)
sdpa_mma_kernel(const float* __restrict__ Qg,
                const unsigned char* __restrict__ Mg,
                float* __restrict__ ctx_out,
                float* __restrict__ w_out)
{
    extern __shared__ char smem[];
    const uint32_t sb = smem_u32(smem);

    const int t    = threadIdx.x;
    const int lane = t & 31;
    const int w    = t >> 5;
    const int wr   = w & 3;        // warp-row: q rows wr*16..+15 (of 64)
    const int wc   = w >> 2;       // warp-col: k quarter 0..3 (32 cols)
    const int tq   = lane >> 2;    // 0..7
    const int tc   = lane & 3;     // 0..3

    const int bh = blockIdx.y;
    const int q0 = blockIdx.x * MQT;
    const size_t row0 = (size_t)bh * S_LEN + q0;
    const int wide = g_mask_wide;

    float*     red    = (float*)(smem + O_RED);
    float*     sinv   = (float*)(smem + O_INV);
    uint32_t*  mcache = (uint32_t*)(smem + O_MC);

    const unsigned char* kvsrc = g_kv16 + (size_t)bh * NCH * CHUNK_B;

    const size_t qrA = row0 + wr * 16 + tq;
    const size_t qrB = qrA + 8;
    const size_t mrowA = qrA * (size_t)S_LEN;
    const size_t mrowB = qrB * (size_t)S_LEN;

    // ---- stage Q (scaled) into swizzled tiles in the mcache region ----
    {
        const float* qs = Qg + row0 * DKD;
        int i = t;                       // 8-float group 0..511
        int row = i >> 3, c8 = i & 7;
        uint32_t o = SWZ((uint32_t)(row * 128 + c8 * 16));
        float4 a = *(const float4*)(qs + row * DKD + c8 * 8);
        float4 b = *(const float4*)(qs + row * DKD + c8 * 8 + 4);
        a.x *= QSCALE; a.y *= QSCALE; a.z *= QSCALE; a.w *= QSCALE;
        b.x *= QSCALE; b.y *= QSCALE; b.z *= QSCALE; b.w *= QSCALE;
        uint4 H, L;
        split2(a.x, a.y, H.x, L.x); split2(a.z, a.w, H.y, L.y);
        split2(b.x, b.y, H.z, L.z); split2(b.z, b.w, H.w, L.w);
        *(uint4*)(smem + O_MC + o)           = H;
        *(uint4*)(smem + O_MC + QTILE_B + o) = L;
    }
    __syncthreads();

    // ---- Q A-frags resident for entire kernel ----
    uint32_t QAh[4][4], QAl[4][4];
#pragma unroll
    for (int s = 0; s < 4; ++s) {
        uint32_t off = SWZ((uint32_t)((wr * 16 + (lane & 15)) * 128 + s * 32 + (lane >> 4) * 16));
        ldsm4(sb + O_MC + off,           QAh[s][0], QAh[s][1], QAh[s][2], QAh[s][3]);
        ldsm4(sb + O_MC + QTILE_B + off, QAl[s][0], QAl[s][1], QAl[s][2], QAl[s][3]);
    }
    __syncthreads();   // frags loaded; mcache region reusable

    // ---- prologue prefetch chunk0 -> buf0 ----
    dma_tiles(sb + O_BUF0, kvsrc, t, 4096);

    float ctx[8][4] = {};
    float rs0 = 0.f, rs1 = 0.f;

    // ================== PASS 1: S + exp + rowsum + PV ==================
    for (int ch = 0; ch < NCH; ++ch) {
        const int kb = ch * NKC;
        const uint32_t buf = sb + ((ch & 1) ? O_BUF1 : O_BUF0);

        CPWAIT0();
        __syncthreads();   // chunk ch ready; prev compute done everywhere
        if (ch + 1 < NCH)
            dma_tiles(sb + ((ch & 1) ? O_BUF0 : O_BUF1),
                      kvsrc + (size_t)(ch + 1) * CHUNK_B, t, 4096);

        // mask bits (gather early; cache for pass 2)
        uint32_t mk = 0;
#pragma unroll
        for (int j = 0; j < 4; ++j) {
            int col = kb + wc * 32 + j * 8 + 2 * tc;
            uint32_t b0, b1, b2, b3;
            if (wide) {
                uint2 a = *(const uint2*)((const unsigned*)Mg + mrowA + col);
                uint2 b = *(const uint2*)((const unsigned*)Mg + mrowB + col);
                b0 = a.x != 0u; b1 = a.y != 0u; b2 = b.x != 0u; b3 = b.y != 0u;
            } else {
                unsigned short a = *(const unsigned short*)(Mg + mrowA + col);
                unsigned short b = *(const unsigned short*)(Mg + mrowB + col);
                b0 = (a & 0xFF) != 0; b1 = (a >> 8) != 0;
                b2 = (b & 0xFF) != 0; b3 = (b >> 8) != 0;
            }
            mk |= (b0 << (4 * j)) | (b1 << (4 * j + 1)) | (b2 << (4 * j + 2)) | (b3 << (4 * j + 3));
        }
        mcache[ch * THREADS + t] = mk;

        // S phase
        float acc[4][4] = {};
        s_phase_res(buf, buf + TILE_B, QAh, QAl, acc, lane, wc);

        // mask + exp2 + rowsum
#pragma unroll
        for (int j = 0; j < 4; ++j) {
            float e0 = ((mk >> (4 * j)) & 1u)     ? 0.f : ex2f(acc[j][0]);
            float e1 = ((mk >> (4 * j + 1)) & 1u) ? 0.f : ex2f(acc[j][1]);
            float e2 = ((mk >> (4 * j + 2)) & 1u) ? 0.f : ex2f(acc[j][2]);
            float e3 = ((mk >> (4 * j + 3)) & 1u) ? 0.f : ex2f(acc[j][3]);
            rs0 += e0 + e1;  rs1 += e2 + e3;
            acc[j][0] = e0; acc[j][1] = e1; acc[j][2] = e2; acc[j][3] = e3;
        }

        // repack P as bf16 hi/lo A-frags (2 k16 frags over this warp's 32 k)
        uint32_t PAh[2][4], PAl[2][4];
#pragma unroll
        for (int s = 0; s < 2; ++s) {
            split2(acc[2 * s][0],     acc[2 * s][1],     PAh[s][0], PAl[s][0]);
            split2(acc[2 * s][2],     acc[2 * s][3],     PAh[s][1], PAl[s][1]);
            split2(acc[2 * s + 1][0], acc[2 * s + 1][1], PAh[s][2], PAl[s][2]);
            split2(acc[2 * s + 1][2], acc[2 * s + 1][3], PAh[s][3], PAl[s][3]);
        }

        // PV phase: V rows wc*32..+31
        const uint32_t vhi = buf + 2 * TILE_B, vlo = buf + 3 * TILE_B;
#pragma unroll
        for (int s = 0; s < 2; ++s) {
#pragma unroll
            for (int j2 = 0; j2 < 4; ++j2) {
                uint32_t o = SWZ((uint32_t)((wc * 32 + s * 16 + (lane & 15)) * 128
                                            + j2 * 32 + (lane >> 4) * 16));
                uint32_t bh0, bh1, bh2, bh3, bl0, bl1, bl2, bl3;
                ldsm4t(vhi + o, bh0, bh1, bh2, bh3);
                ldsm4t(vlo + o, bl0, bl1, bl2, bl3);
                mma16816(ctx[2 * j2],     PAh[s], bh0, bh1);
                mma16816(ctx[2 * j2],     PAl[s], bh0, bh1);
                mma16816(ctx[2 * j2],     PAh[s], bl0, bl1);
                mma16816(ctx[2 * j2 + 1], PAh[s], bh2, bh3);
                mma16816(ctx[2 * j2 + 1], PAl[s], bh2, bh3);
                mma16816(ctx[2 * j2 + 1], PAh[s], bl2, bl3);
            }
        }
    }

    __syncthreads();   // everyone done with buffers
    // pass-2 prefetch: K tiles of chunk0 -> buf0 (32 KB)
    dma_tiles(sb + O_BUF0, kvsrc, t, 2048);

    // ================= row-sum reduction =================
    if (t < 64) red[t] = 0.f;
    __syncthreads();
    rs0 += __shfl_xor_sync(0xffffffffu, rs0, 1);
    rs0 += __shfl_xor_sync(0xffffffffu, rs0, 2);
    rs1 += __shfl_xor_sync(0xffffffffu, rs1, 1);
    rs1 += __shfl_xor_sync(0xffffffffu, rs1, 2);
    if (tc == 0) {
        atomicAdd(&red[wr * 16 + tq], rs0);
        atomicAdd(&red[wr * 16 + tq + 8], rs1);
    }
    // ctx partials into buf1 (dead until pass-2 chunk1): 4 groups x 64x64 fp32
    {
        float* cbuf = (float*)(smem + O_BUF1) + wc * 4096;
#pragma unroll
        for (int j = 0; j < 8; ++j) {
            int row = wr * 16 + tq, col = j * 8 + 2 * tc;
            *(float2*)(cbuf + row * 64 + col)       = make_float2(ctx[j][0], ctx[j][1]);
            *(float2*)(cbuf + (row + 8) * 64 + col) = make_float2(ctx[j][2], ctx[j][3]);
        }
    }
    __syncthreads();
    if (t < 64) sinv[t] = 1.0f / red[t];
    __syncthreads();

    // ================= ctx combine (4 groups) + write =================
    {
        const float4* b0 = (const float4*)(smem + O_BUF1);
#pragma unroll
        for (int kk = 0; kk < 2; ++kk) {
            int i = t + kk * THREADS;       // float4 idx 0..1023
            int row = i >> 4, c4 = i & 15;
            float4 a = b0[i], b = b0[i + 1024], c = b0[i + 2048], d = b0[i + 3072];
            float iv = sinv[row];
            float4 o;
            o.x = (a.x + b.x + c.x + d.x) * iv;
            o.y = (a.y + b.y + c.y + d.y) * iv;
            o.z = (a.z + b.z + c.z + d.z) * iv;
            o.w = (a.w + b.w + c.w + d.w) * iv;
            *(float4*)(ctx_out + (row0 + row) * DKD + c4 * 4) = o;
        }
    }
    __syncthreads();   // buf1 free again

    // ================== PASS 2: recompute S, write normalized weights ==================
    const float ivA = sinv[wr * 16 + tq];
    const float ivB = sinv[wr * 16 + tq + 8];
    for (int ch = 0; ch < NCH; ++ch) {
        const int kb = ch * NKC;
        const uint32_t buf = sb + ((ch & 1) ? O_BUF1 : O_BUF0);

        CPWAIT0();
        __syncthreads();
        if (ch + 1 < NCH)
            dma_tiles(sb + ((ch & 1) ? O_BUF0 : O_BUF1),
                      kvsrc + (size_t)(ch + 1) * CHUNK_B, t, 2048);

        float acc[4][4] = {};
        s_phase_res(buf, buf + TILE_B, QAh, QAl, acc, lane, wc);

        const uint32_t mk = mcache[ch * THREADS + t];
#pragma unroll
        for (int j = 0; j < 4; ++j) {
            float e0 = ((mk >> (4 * j)) & 1u)     ? 0.f : ex2f(acc[j][0]) * ivA;
            float e1 = ((mk >> (4 * j + 1)) & 1u) ? 0.f : ex2f(acc[j][1]) * ivA;
            float e2 = ((mk >> (4 * j + 2)) & 1u) ? 0.f : ex2f(acc[j][2]) * ivB;
            float e3 = ((mk >> (4 * j + 3)) & 1u) ? 0.f : ex2f(acc[j][3]) * ivB;
            int col = kb + wc * 32 + j * 8 + 2 * tc;
            __stcs((float2*)(w_out + mrowA + col), make_float2(e0, e1));
            __stcs((float2*)(w_out + mrowB + col), make_float2(e2, e3));
        }
    }
}

extern "C" void kernel_launch(void* const* d_in, const int* in_sizes, int n_in,
                              void* d_out, int out_size)
{
    const float*         Q = (const float*)d_in[0];
    const float*         K = (const float*)d_in[1];
    const float*         V = (const float*)d_in[2];
    const unsigned char* M = (const unsigned char*)d_in[3];

    float* ctx = (float*)d_out;
    float* wts = (float*)d_out + (size_t)BHN * S_LEN * DKD;

    cudaFuncSetAttribute(sdpa_mma_kernel,
                         cudaFuncAttributeMaxDynamicSharedMemorySize, SMEMB);

    detect_mask_kind_kernel<<<1, 256>>>((const unsigned*)M);
    preconvert_kernel<<<dim3(NCH, BHN), 256>>>(K, V);

    dim3 grid(S_LEN / MQT, BHN);   // (32, 32) = 1024 CTAs
    sdpa_mma_kernel<<<grid, THREADS, SMEMB>>>(Q, M, ctx, wts);
}

// round 10
// speedup vs baseline: 8.2586x; 1.1216x over previous
#include <cuda_runtime.h>
#include <cuda_bf16.h>
#include <cstdint>
#include <cstddef>

#define S_LEN   2048
#define DKD     64
#define BHN     32
#define MQT     64           // q rows per CTA
#define NKC     64           // k cols per chunk
#define NCH     (S_LEN / NKC)   // 32
#define THREADS 256

// 0.125 * log2(e): fold softmax scale + exp->exp2 conversion into Q
#define QSCALE 0.1803368801111831f

#define TILE_B  8192         // one 64x64 bf16 K/V tile, SW128 swizzled, 128B rows
#define CHUNK_B 32768        // Khi,Klo,Vhi,Vlo per chunk
#define QTILE_B 8192         // 64x64 bf16 Q tile

// ---- smem byte offsets ----
#define O_BUF0 0
#define O_BUF1 32768
#define O_MC   65536         // mask cache 16KB (uint16/thread/chunk); doubles as Q staging
#define O_RED  81920         // 64 floats
#define O_INV  82176         // 64 floats
#define SMEMB  82432

#define SWZ(o) ((o) ^ (((o) >> 3) & 0x70))

// bf16 hi/lo K,V tiles, pre-swizzled ldmatrix-ready images (32 MB scratch)
__device__ __align__(16) unsigned char g_kv16[(size_t)BHN * NCH * CHUNK_B];
__device__ int g_mask_wide;

// ---------------- helpers ----------------
__device__ __forceinline__ uint32_t smem_u32(const void* p) {
    uint32_t a;
    asm("{ .reg .u64 t; cvta.to.shared.u64 t, %1; cvt.u32.u64 %0, t; }" : "=r"(a) : "l"(p));
    return a;
}
__device__ __forceinline__ float ex2f(float x) {
    float y; asm("ex2.approx.f32 %0, %1;" : "=f"(y) : "f"(x)); return y;
}
__device__ __forceinline__ uint32_t pkbf(float lo, float hi) {  // lo -> bits[15:0]
    uint32_t r; asm("cvt.rn.bf16x2.f32 %0, %1, %2;" : "=r"(r) : "f"(hi), "f"(lo)); return r;
}
__device__ __forceinline__ void ldsm4(uint32_t a, uint32_t& r0, uint32_t& r1, uint32_t& r2, uint32_t& r3) {
    asm volatile("ldmatrix.sync.aligned.m8n8.x4.shared.b16 {%0,%1,%2,%3}, [%4];"
                 : "=r"(r0), "=r"(r1), "=r"(r2), "=r"(r3) : "r"(a));
}
__device__ __forceinline__ void ldsm4t(uint32_t a, uint32_t& r0, uint32_t& r1, uint32_t& r2, uint32_t& r3) {
    asm volatile("ldmatrix.sync.aligned.m8n8.x4.trans.shared.b16 {%0,%1,%2,%3}, [%4];"
                 : "=r"(r0), "=r"(r1), "=r"(r2), "=r"(r3) : "r"(a));
}
__device__ __forceinline__ void mma16816(float* c, const uint32_t* A, uint32_t b0, uint32_t b1) {
    asm volatile("mma.sync.aligned.m16n8k16.row.col.f32.bf16.bf16.f32 "
                 "{%0,%1,%2,%3}, {%4,%5,%6,%7}, {%8,%9}, {%0,%1,%2,%3};"
                 : "+f"(c[0]), "+f"(c[1]), "+f"(c[2]), "+f"(c[3])
                 : "r"(A[0]), "r"(A[1]), "r"(A[2]), "r"(A[3]), "r"(b0), "r"(b1));
}
#define CP16(dst, src) asm volatile("cp.async.cg.shared.global [%0], [%1], 16;" :: "r"(dst), "l"(src))
#define CPCOMMIT()     asm volatile("cp.async.commit_group;" ::: "memory")
#define CPWAIT0()      asm volatile("cp.async.wait_group 0;" ::: "memory")

// split fp32 -> bf16 hi + bf16 residual(lo)
__device__ __forceinline__ void split2(float x0, float x1, uint32_t& hi, uint32_t& lo) {
    __nv_bfloat16 b0 = __float2bfloat16(x0), b1 = __float2bfloat16(x1);
    hi = (uint32_t)__bfloat16_as_ushort(b0) | ((uint32_t)__bfloat16_as_ushort(b1) << 16);
    lo = pkbf(x0 - __bfloat162float(b0), x1 - __bfloat162float(b1));
}

// ---------------- preprocessing: K/V fp32 -> swizzled bf16 hi/lo tiles (+mask detect) ----------------
__global__ void preconvert_kernel(const float* __restrict__ K, const float* __restrict__ V,
                                  const unsigned* __restrict__ mw) {
    const int ch = blockIdx.x, bh = blockIdx.y, t = threadIdx.x;   // 256 threads
    if (ch == 0 && bh == 0) {   // fold mask-kind detection into this launch
        __shared__ int s_i32bad, s_f32bad;
        if (t == 0) { s_i32bad = 0; s_f32bad = 0; }
        __syncthreads();
        for (int i = t; i < 1024; i += 256) {
            unsigned w = mw[i];
            if (w > 1u)                      atomicOr(&s_i32bad, 1);
            if (w != 0u && w != 0x3F800000u) atomicOr(&s_f32bad, 1);
        }
        __syncthreads();
        if (t == 0) g_mask_wide = (!s_i32bad || !s_f32bad) ? 1 : 0;
    }
    const float* ks = K + ((size_t)bh * S_LEN + ch * NKC) * DKD;
    const float* vs = V + ((size_t)bh * S_LEN + ch * NKC) * DKD;
    unsigned char* dst = g_kv16 + ((size_t)bh * NCH + ch) * CHUNK_B;
#pragma unroll
    for (int it = 0; it < 2; ++it) {
        int i = t + it * 256;           // 8-float group 0..511
        int row = i >> 3, c8 = i & 7;
        uint32_t o = SWZ((uint32_t)(row * 128 + c8 * 16));
        float4 a = *(const float4*)(ks + row * DKD + c8 * 8);
        float4 b = *(const float4*)(ks + row * DKD + c8 * 8 + 4);
        uint4 H, L;
        split2(a.x, a.y, H.x, L.x); split2(a.z, a.w, H.y, L.y);
        split2(b.x, b.y, H.z, L.z); split2(b.z, b.w, H.w, L.w);
        *(uint4*)(dst + o)          = H;
        *(uint4*)(dst + TILE_B + o) = L;
        a = *(const float4*)(vs + row * DKD + c8 * 8);
        b = *(const float4*)(vs + row * DKD + c8 * 8 + 4);
        split2(a.x, a.y, H.x, L.x); split2(a.z, a.w, H.y, L.y);
        split2(b.x, b.y, H.z, L.z); split2(b.z, b.w, H.w, L.w);
        *(uint4*)(dst + 2 * TILE_B + o) = H;
        *(uint4*)(dst + 3 * TILE_B + o) = L;
    }
}

// copy 16*n16 bytes from scratch gmem -> smem buffer
__device__ __forceinline__ void dma_tiles(uint32_t dst, const unsigned char* src, int t, int n16) {
#pragma unroll
    for (int kk = 0; kk < 8; ++kk) {
        if (kk * THREADS >= n16) break;
        int i = t + kk * THREADS;
        CP16(dst + i * 16, src + (size_t)i * 16);
    }
    CPCOMMIT();
}

// S phase (warp covers 16 q x 32 k): 4 j-frags, 12 mma each
__device__ __forceinline__ void s_phase_res(uint32_t khi, uint32_t klo,
                                            const uint32_t QAh[4][4], const uint32_t QAl[4][4],
                                            float acc[4][4], int lane, int wc) {
#pragma unroll
    for (int j = 0; j < 4; ++j) {
        uint32_t base = (uint32_t)((wc * 32 + j * 8 + (lane & 7)) * 128 + (lane >> 3) * 16);
        uint32_t o0 = SWZ(base), o1 = SWZ(base + 64);
        uint32_t h0, h1, h2, h3, l0, l1, l2, l3;
        ldsm4(khi + o0, h0, h1, h2, h3);
        mma16816(acc[j], QAh[0], h0, h1);
        mma16816(acc[j], QAh[1], h2, h3);
        mma16816(acc[j], QAl[0], h0, h1);
        mma16816(acc[j], QAl[1], h2, h3);
        ldsm4(klo + o0, l0, l1, l2, l3);
        mma16816(acc[j], QAh[0], l0, l1);
        mma16816(acc[j], QAh[1], l2, l3);
        ldsm4(khi + o1, h0, h1, h2, h3);
        mma16816(acc[j], QAh[2], h0, h1);
        mma16816(acc[j], QAh[3], h2, h3);
        mma16816(acc[j], QAl[2], h0, h1);
        mma16816(acc[j], QAl[3], h2, h3);
        ldsm4(klo + o1, l0, l1, l2, l3);
        mma16816(acc[j], QAh[2], l0, l1);
        mma16816(acc[j], QAh[3], l2, l3);
    }
}

__global__ void __launch_bounds__(THREADS, 2)
sdpa_mma_kernel(const float* __restrict__ Qg,
                const unsigned char* __restrict__ Mg,
                float* __restrict__ ctx_out,
                float* __restrict__ w_out)
{
    extern __shared__ char smem[];
    const uint32_t sb = smem_u32(smem);

    const int t    = threadIdx.x;
    const int lane = t & 31;
    const int w    = t >> 5;       // 0..7
    const int wr   = w & 3;        // warp-row: q rows wr*16..+15 (of 64)
    const int wc   = w >> 2;       // warp-col: k half 0/1 (32 cols of 64)
    const int tq   = lane >> 2;    // 0..7
    const int tc   = lane & 3;     // 0..3

    const int bh = blockIdx.y;
    const int q0 = blockIdx.x * MQT;
    const size_t row0 = (size_t)bh * S_LEN + q0;
    const int wide = g_mask_wide;

    float*          red    = (float*)(smem + O_RED);
    float*          sinv   = (float*)(smem + O_INV);
    unsigned short* mcache = (unsigned short*)(smem + O_MC);

    const unsigned char* kvsrc = g_kv16 + (size_t)bh * NCH * CHUNK_B;

    const size_t qrA = row0 + wr * 16 + tq;
    const size_t qrB = qrA + 8;
    const size_t mrowA = qrA * (size_t)S_LEN;
    const size_t mrowB = qrB * (size_t)S_LEN;

    // ---- stage Q (scaled) into swizzled tiles in the mcache region ----
    {
        const float* qs = Qg + row0 * DKD;
#pragma unroll
        for (int it = 0; it < 2; ++it) {
            int i = t + it * THREADS;        // 8-float group 0..511
            int row = i >> 3, c8 = i & 7;
            uint32_t o = SWZ((uint32_t)(row * 128 + c8 * 16));
            float4 a = *(const float4*)(qs + row * DKD + c8 * 8);
            float4 b = *(const float4*)(qs + row * DKD + c8 * 8 + 4);
            a.x *= QSCALE; a.y *= QSCALE; a.z *= QSCALE; a.w *= QSCALE;
            b.x *= QSCALE; b.y *= QSCALE; b.z *= QSCALE; b.w *= QSCALE;
            uint4 H, L;
            split2(a.x, a.y, H.x, L.x); split2(a.z, a.w, H.y, L.y);
            split2(b.x, b.y, H.z, L.z); split2(b.z, b.w, H.w, L.w);
            *(uint4*)(smem + O_MC + o)           = H;
            *(uint4*)(smem + O_MC + QTILE_B + o) = L;   // NOTE: QTILE_B == MC size/2
        }
    }
    __syncthreads();

    // ---- Q A-frags resident for entire kernel ----
    uint32_t QAh[4][4], QAl[4][4];
#pragma unroll
    for (int s = 0; s < 4; ++s) {
        uint32_t off = SWZ((uint32_t)((wr * 16 + (lane & 15)) * 128 + s * 32 + (lane >> 4) * 16));
        ldsm4(sb + O_MC + off,           QAh[s][0], QAh[s][1], QAh[s][2], QAh[s][3]);
        ldsm4(sb + O_MC + QTILE_B + off, QAl[s][0], QAl[s][1], QAl[s][2], QAl[s][3]);
    }
    __syncthreads();   // frags loaded; mcache region reusable

    // ---- prologue prefetch chunk0 -> buf0 ----
    dma_tiles(sb + O_BUF0, kvsrc, t, CHUNK_B / 16);

    float ctx[8][4] = {};
    float rs0 = 0.f, rs1 = 0.f;

    // ================== PASS 1: S + exp + rowsum + PV ==================
    for (int ch = 0; ch < NCH; ++ch) {
        const int kb = ch * NKC;
        const uint32_t buf = sb + ((ch & 1) ? O_BUF1 : O_BUF0);

        CPWAIT0();
        __syncthreads();   // chunk ch ready; prev compute done everywhere
        if (ch + 1 < NCH)
            dma_tiles(sb + ((ch & 1) ? O_BUF0 : O_BUF1),
                      kvsrc + (size_t)(ch + 1) * CHUNK_B, t, CHUNK_B / 16);

        // mask bits (gather early; cache for pass 2)
        uint32_t mk = 0;
#pragma unroll
        for (int j = 0; j < 4; ++j) {
            int col = kb + wc * 32 + j * 8 + 2 * tc;
            uint32_t b0, b1, b2, b3;
            if (wide) {
                uint2 a = *(const uint2*)((const unsigned*)Mg + mrowA + col);
                uint2 b = *(const uint2*)((const unsigned*)Mg + mrowB + col);
                b0 = a.x != 0u; b1 = a.y != 0u; b2 = b.x != 0u; b3 = b.y != 0u;
            } else {
                unsigned short a = *(const unsigned short*)(Mg + mrowA + col);
                unsigned short b = *(const unsigned short*)(Mg + mrowB + col);
                b0 = (a & 0xFF) != 0; b1 = (a >> 8) != 0;
                b2 = (b & 0xFF) != 0; b3 = (b >> 8) != 0;
            }
            mk |= (b0 << (4 * j)) | (b1 << (4 * j + 1)) | (b2 << (4 * j + 2)) | (b3 << (4 * j + 3));
        }
        mcache[ch * THREADS + t] = (unsigned short)mk;

        // S phase
        float acc[4][4] = {};
        s_phase_res(buf, buf + TILE_B, QAh, QAl, acc, lane, wc);

        // mask + exp2 + rowsum
#pragma unroll
        for (int j = 0; j < 4; ++j) {
            float e0 = ((mk >> (4 * j)) & 1u)     ? 0.f : ex2f(acc[j][0]);
            float e1 = ((mk >> (4 * j + 1)) & 1u) ? 0.f : ex2f(acc[j][1]);
            float e2 = ((mk >> (4 * j + 2)) & 1u) ? 0.f : ex2f(acc[j][2]);
            float e3 = ((mk >> (4 * j + 3)) & 1u) ? 0.f : ex2f(acc[j][3]);
            rs0 += e0 + e1;  rs1 += e2 + e3;
            acc[j][0] = e0; acc[j][1] = e1; acc[j][2] = e2; acc[j][3] = e3;
        }

        // repack P as bf16 hi/lo A-frags (2 k16 frags over this warp's 32 k)
        uint32_t PAh[2][4], PAl[2][4];
#pragma unroll
        for (int s = 0; s < 2; ++s) {
            split2(acc[2 * s][0],     acc[2 * s][1],     PAh[s][0], PAl[s][0]);
            split2(acc[2 * s][2],     acc[2 * s][3],     PAh[s][1], PAl[s][1]);
            split2(acc[2 * s + 1][0], acc[2 * s + 1][1], PAh[s][2], PAl[s][2]);
            split2(acc[2 * s + 1][2], acc[2 * s + 1][3], PAh[s][3], PAl[s][3]);
        }

        // PV phase: V rows wc*32..+31
        const uint32_t vhi = buf + 2 * TILE_B, vlo = buf + 3 * TILE_B;
#pragma unroll
        for (int s = 0; s < 2; ++s) {
#pragma unroll
            for (int j2 = 0; j2 < 4; ++j2) {
                uint32_t o = SWZ((uint32_t)((wc * 32 + s * 16 + (lane & 15)) * 128
                                            + j2 * 32 + (lane >> 4) * 16));
                uint32_t bh0, bh1, bh2, bh3, bl0, bl1, bl2, bl3;
                ldsm4t(vhi + o, bh0, bh1, bh2, bh3);
                ldsm4t(vlo + o, bl0, bl1, bl2, bl3);
                mma16816(ctx[2 * j2],     PAh[s], bh0, bh1);
                mma16816(ctx[2 * j2],     PAl[s], bh0, bh1);
                mma16816(ctx[2 * j2],     PAh[s], bl0, bl1);
                mma16816(ctx[2 * j2 + 1], PAh[s], bh2, bh3);
                mma16816(ctx[2 * j2 + 1], PAl[s], bh2, bh3);
                mma16816(ctx[2 * j2 + 1], PAh[s], bl2, bl3);
            }
        }
    }

    __syncthreads();   // everyone done with buffers
    // pass-2 prefetch: K tiles of chunk0 -> buf0 (16 KB)
    dma_tiles(sb + O_BUF0, kvsrc, t, 2 * TILE_B / 16);

    // ================= row-sum reduction =================
    if (t < 64) red[t] = 0.f;
    __syncthreads();
    rs0 += __shfl_xor_sync(0xffffffffu, rs0, 1);
    rs0 += __shfl_xor_sync(0xffffffffu, rs0, 2);
    rs1 += __shfl_xor_sync(0xffffffffu, rs1, 1);
    rs1 += __shfl_xor_sync(0xffffffffu, rs1, 2);
    if (tc == 0) {
        atomicAdd(&red[wr * 16 + tq], rs0);
        atomicAdd(&red[wr * 16 + tq + 8], rs1);
    }
    // ctx partials into buf1 (dead until pass-2 chunk1): 2 groups x 64x64 fp32
    {
        float* cbuf = (float*)(smem + O_BUF1) + wc * 4096;
#pragma unroll
        for (int j = 0; j < 8; ++j) {
            int row = wr * 16 + tq, col = j * 8 + 2 * tc;
            *(float2*)(cbuf + row * 64 + col)       = make_float2(ctx[j][0], ctx[j][1]);
            *(float2*)(cbuf + (row + 8) * 64 + col) = make_float2(ctx[j][2], ctx[j][3]);
        }
    }
    __syncthreads();
    if (t < 64) sinv[t] = 1.0f / red[t];
    __syncthreads();

    // ================= ctx combine (2 groups) + write =================
    {
        const float4* b0 = (const float4*)(smem + O_BUF1);
#pragma unroll
        for (int kk = 0; kk < 4; ++kk) {
            int i = t + kk * THREADS;       // float4 idx 0..1023
            int row = i >> 4, c4 = i & 15;
            float4 a = b0[i], b = b0[i + 1024];
            float iv = sinv[row];
            float4 o;
            o.x = (a.x + b.x) * iv;
            o.y = (a.y + b.y) * iv;
            o.z = (a.z + b.z) * iv;
            o.w = (a.w + b.w) * iv;
            *(float4*)(ctx_out + (row0 + row) * DKD + c4 * 4) = o;
        }
    }
    __syncthreads();   // buf1 free again

    // ================== PASS 2: recompute S, write normalized weights ==================
    const float ivA = sinv[wr * 16 + tq];
    const float ivB = sinv[wr * 16 + tq + 8];
    for (int ch = 0; ch < NCH; ++ch) {
        const int kb = ch * NKC;
        const uint32_t buf = sb + ((ch & 1) ? O_BUF1 : O_BUF0);

        CPWAIT0();
        __syncthreads();
        if (ch + 1 < NCH)
            dma_tiles(sb + ((ch & 1) ? O_BUF0 : O_BUF1),
                      kvsrc + (size_t)(ch + 1) * CHUNK_B, t, 2 * TILE_B / 16);

        float acc[4][4] = {};
        s_phase_res(buf, buf + TILE_B, QAh, QAl, acc, lane, wc);

        const uint32_t mk = mcache[ch * THREADS + t];
#pragma unroll
        for (int j = 0; j < 4; ++j) {
            float e0 = ((mk >> (4 * j)) & 1u)     ? 0.f : ex2f(acc[j][0]) * ivA;
            float e1 = ((mk >> (4 * j + 1)) & 1u) ? 0.f : ex2f(acc[j][1]) * ivA;
            float e2 = ((mk >> (4 * j + 2)) & 1u) ? 0.f : ex2f(acc[j][2]) * ivB;
            float e3 = ((mk >> (4 * j + 3)) & 1u) ? 0.f : ex2f(acc[j][3]) * ivB;
            int col = kb + wc * 32 + j * 8 + 2 * tc;
            __stcs((float2*)(w_out + mrowA + col), make_float2(e0, e1));
            __stcs((float2*)(w_out + mrowB + col), make_float2(e2, e3));
        }
    }
}

extern "C" void kernel_launch(void* const* d_in, const int* in_sizes, int n_in,
                              void* d_out, int out_size)
{
    const float*         Q = (const float*)d_in[0];
    const float*         K = (const float*)d_in[1];
    const float*         V = (const float*)d_in[2];
    const unsigned char* M = (const unsigned char*)d_in[3];

    float* ctx = (float*)d_out;
    float* wts = (float*)d_out + (size_t)BHN * S_LEN * DKD;

    cudaFuncSetAttribute(sdpa_mma_kernel,
                         cudaFuncAttributeMaxDynamicSharedMemorySize, SMEMB);

    preconvert_kernel<<<dim3(NCH, BHN), 256>>>(K, V, (const unsigned*)M);

    dim3 grid(S_LEN / MQT, BHN);   // (32, 32) = 1024 CTAs, 2 resident per SM
    sdpa_mma_kernel<<<grid, THREADS, SMEMB>>>(Q, M, ctx, wts);
}